// round 1
// baseline (speedup 1.0000x reference)
#include <cuda_runtime.h>
#include <cuda_bf16.h>
#include <math.h>

// Problem constants
#define BATCH 4
#define TSEQ 2048
#define DMODEL 1024
#define NHEAD 16
#define DHEAD 64
#define DFF 4096
#define MROWS (BATCH * TSEQ)   // 8192

// ---------------------------------------------------------------------------
// Scratch (device globals; no runtime allocation allowed)
// ---------------------------------------------------------------------------
__device__ float g_ln[(size_t)MROWS * DMODEL];    // 32 MB
__device__ float g_qkv[(size_t)MROWS * 3 * DMODEL]; // 96 MB
__device__ float g_ao[(size_t)MROWS * DMODEL];    // 32 MB
__device__ float g_x1[(size_t)MROWS * DMODEL];    // 32 MB
__device__ float g_ff[(size_t)MROWS * DFF];       // 128 MB

// ---------------------------------------------------------------------------
// LayerNorm: one block per row, 256 threads, row length 1024 (4 floats/thread)
// ---------------------------------------------------------------------------
__global__ __launch_bounds__(256)
void ln_kernel(const float* __restrict__ x, const float* __restrict__ sc,
               const float* __restrict__ bi, float* __restrict__ y) {
    const int row = blockIdx.x;
    const int t = threadIdx.x;
    const float4 v = *(const float4*)(x + (size_t)row * DMODEL + t * 4);
    float s = v.x + v.y + v.z + v.w;
    float s2 = v.x * v.x + v.y * v.y + v.z * v.z + v.w * v.w;
#pragma unroll
    for (int o = 16; o; o >>= 1) {
        s  += __shfl_xor_sync(0xffffffffu, s, o);
        s2 += __shfl_xor_sync(0xffffffffu, s2, o);
    }
    __shared__ float rs[8], rs2[8];
    if ((t & 31) == 0) { rs[t >> 5] = s; rs2[t >> 5] = s2; }
    __syncthreads();
    s = 0.f; s2 = 0.f;
#pragma unroll
    for (int i = 0; i < 8; i++) { s += rs[i]; s2 += rs2[i]; }
    const float mu = s * (1.0f / DMODEL);
    const float var = s2 * (1.0f / DMODEL) - mu * mu;
    const float r = rsqrtf(var + 1e-5f);
    const float4 g4 = *(const float4*)(sc + t * 4);
    const float4 b4 = *(const float4*)(bi + t * 4);
    float4 o4;
    o4.x = (v.x - mu) * r * g4.x + b4.x;
    o4.y = (v.y - mu) * r * g4.y + b4.y;
    o4.z = (v.z - mu) * r * g4.z + b4.z;
    o4.w = (v.w - mu) * r * g4.w + b4.w;
    *(float4*)(y + (size_t)row * DMODEL + t * 4) = o4;
}

// ---------------------------------------------------------------------------
// SGEMM: C[M,N] = A[M,K] @ W[N,K]^T  (torch Linear layout), fused epilogues
//   EPI 0: none
//   EPI 1: + res[M,N]
//   EPI 2: + bias[N], then exact GELU
//   EPI 3: + bias[N] + res[M,N]
// Tiles: 128x128x16, 256 threads, 8x8 per thread.
// All dims assumed multiples of 128 (true here).
// ---------------------------------------------------------------------------
__device__ __forceinline__ float gelu_exact(float x) {
    return 0.5f * x * (1.0f + erff(x * 0.70710678118654752f));
}

template <int EPI>
__global__ __launch_bounds__(256)
void gemm_nt(const float* __restrict__ A, const float* __restrict__ W,
             float* __restrict__ C, int M, int N, int K,
             const float* __restrict__ bias, const float* __restrict__ res) {
    __shared__ float As[16][128];
    __shared__ float Bs[16][128];
    const int bm = blockIdx.y * 128;
    const int bn = blockIdx.x * 128;
    const int tid = threadIdx.x;
    const int tr = tid >> 4;          // 0..15 -> rows tr*8..tr*8+7
    const int tc = tid & 15;          // 0..15 -> cols tc*4 and 64+tc*4
    const int lr = tid >> 2;          // 0..63 load row
    const int lc = (tid & 3) << 2;    // 0,4,8,12 load col (K dir)

    const float* Ag = A + (size_t)(bm + lr) * K + lc;
    const float* Wg = W + (size_t)(bn + lr) * K + lc;

    float acc[8][8];
#pragma unroll
    for (int i = 0; i < 8; i++)
#pragma unroll
        for (int j = 0; j < 8; j++) acc[i][j] = 0.f;

    for (int kt = 0; kt < K; kt += 16) {
#pragma unroll
        for (int p = 0; p < 2; p++) {
            const float4 a = *(const float4*)(Ag + (size_t)p * 64 * K + kt);
            As[lc + 0][lr + p * 64] = a.x;
            As[lc + 1][lr + p * 64] = a.y;
            As[lc + 2][lr + p * 64] = a.z;
            As[lc + 3][lr + p * 64] = a.w;
            const float4 b = *(const float4*)(Wg + (size_t)p * 64 * K + kt);
            Bs[lc + 0][lr + p * 64] = b.x;
            Bs[lc + 1][lr + p * 64] = b.y;
            Bs[lc + 2][lr + p * 64] = b.z;
            Bs[lc + 3][lr + p * 64] = b.w;
        }
        __syncthreads();
#pragma unroll
        for (int k = 0; k < 16; k++) {
            float a[8], b[8];
            *(float4*)&a[0] = *(const float4*)&As[k][tr * 8];
            *(float4*)&a[4] = *(const float4*)&As[k][tr * 8 + 4];
            *(float4*)&b[0] = *(const float4*)&Bs[k][tc * 4];
            *(float4*)&b[4] = *(const float4*)&Bs[k][64 + tc * 4];
#pragma unroll
            for (int i = 0; i < 8; i++)
#pragma unroll
                for (int j = 0; j < 8; j++)
                    acc[i][j] = fmaf(a[i], b[j], acc[i][j]);
        }
        __syncthreads();
    }

#pragma unroll
    for (int i = 0; i < 8; i++) {
        const int row = bm + tr * 8 + i;
#pragma unroll
        for (int half = 0; half < 2; half++) {
            const int col = bn + half * 64 + tc * 4;
            float4 v;
            v.x = acc[i][half * 4 + 0];
            v.y = acc[i][half * 4 + 1];
            v.z = acc[i][half * 4 + 2];
            v.w = acc[i][half * 4 + 3];
            if (EPI == 2 || EPI == 3) {
                const float4 bb = *(const float4*)&bias[col];
                v.x += bb.x; v.y += bb.y; v.z += bb.z; v.w += bb.w;
            }
            if (EPI == 2) {
                v.x = gelu_exact(v.x);
                v.y = gelu_exact(v.y);
                v.z = gelu_exact(v.z);
                v.w = gelu_exact(v.w);
            }
            if (EPI == 1 || EPI == 3) {
                const float4 rr = *(const float4*)&res[(size_t)row * N + col];
                v.x += rr.x; v.y += rr.y; v.z += rr.z; v.w += rr.w;
            }
            *(float4*)&C[(size_t)row * N + col] = v;
        }
    }
}

// ---------------------------------------------------------------------------
// Fused attention (flash-style): grid (T/64, H, B), 256 threads.
// Each block: 64 queries x full KV sweep (tiles of 64), dh=64.
// qkv layout: row m=(b*T+t), cols [0,1024)=Q, [1024,2048)=K, [2048,3072)=V,
// head h occupies 64 consecutive cols inside each third.
// Thread (ty,tx): ty=tid/16, tx=tid%16; owns 4 rows (ty*4+i) and 4 cols (tx*4+j).
// Row-group softmax stats reduced over the 16 tx lanes via shfl (xor 8,4,2,1).
// ---------------------------------------------------------------------------
#define ATTN_S 68  // smem row stride (floats), 16B-aligned, de-conflicts transpose
#define ATTN_SMEM (3 * 64 * ATTN_S * 4)

__global__ __launch_bounds__(256)
void attn_kernel(const float* __restrict__ qkv, float* __restrict__ ao) {
    extern __shared__ float sm[];
    float* Qs = sm;                     // [q][d], Q pre-scaled by 1/sqrt(dh)
    float* KP = sm + 64 * ATTN_S;       // K^T [d][c] during S; P [q][c] after
    float* Vs = sm + 2 * 64 * ATTN_S;   // [c][d]

    const int b = blockIdx.z, h = blockIdx.y, qt = blockIdx.x;
    const int tid = threadIdx.x;
    const int ty = tid >> 4, tx = tid & 15;
    const int hoff = h * DHEAD;
    const int rowbase = b * TSEQ + qt * 64;

    // Load Q tile (scaled)
#pragma unroll
    for (int p = 0; p < 4; p++) {
        const int idx = tid + p * 256;
        const int r = idx >> 4;
        const int c = (idx & 15) * 4;
        const float4 q = *(const float4*)&qkv[(size_t)(rowbase + r) * 3072 + hoff + c];
        float* dst = &Qs[r * ATTN_S + c];
        dst[0] = q.x * 0.125f; dst[1] = q.y * 0.125f;
        dst[2] = q.z * 0.125f; dst[3] = q.w * 0.125f;
    }

    float m_[4], l_[4], acc[4][4];
#pragma unroll
    for (int i = 0; i < 4; i++) {
        m_[i] = -3.0e38f; l_[i] = 0.f;
#pragma unroll
        for (int j = 0; j < 4; j++) acc[i][j] = 0.f;
    }

    for (int kt = 0; kt < TSEQ / 64; kt++) {
        __syncthreads();  // protects previous-iter P/V reads (and first-iter Q)
        const int kvbase = b * TSEQ + kt * 64;
#pragma unroll
        for (int p = 0; p < 4; p++) {
            const int idx = tid + p * 256;
            const int r = idx >> 4;
            const int c = (idx & 15) * 4;
            const float* src = &qkv[(size_t)(kvbase + r) * 3072 + hoff + c];
            const float4 k4 = *(const float4*)(src + 1024);
            KP[(c + 0) * ATTN_S + r] = k4.x;
            KP[(c + 1) * ATTN_S + r] = k4.y;
            KP[(c + 2) * ATTN_S + r] = k4.z;
            KP[(c + 3) * ATTN_S + r] = k4.w;
            const float4 v4 = *(const float4*)(src + 2048);
            *(float4*)&Vs[r * ATTN_S + c] = v4;
        }
        __syncthreads();

        // S = Q K^T  (4x4 per thread)
        float s4[4][4];
#pragma unroll
        for (int i = 0; i < 4; i++)
#pragma unroll
            for (int j = 0; j < 4; j++) s4[i][j] = 0.f;

#pragma unroll
        for (int d4 = 0; d4 < 64; d4 += 4) {
            float qreg[4][4];
#pragma unroll
            for (int i = 0; i < 4; i++)
                *(float4*)qreg[i] = *(const float4*)&Qs[(ty * 4 + i) * ATTN_S + d4];
#pragma unroll
            for (int dd = 0; dd < 4; dd++) {
                const float4 kv = *(const float4*)&KP[(d4 + dd) * ATTN_S + tx * 4];
#pragma unroll
                for (int i = 0; i < 4; i++) {
                    s4[i][0] = fmaf(qreg[i][dd], kv.x, s4[i][0]);
                    s4[i][1] = fmaf(qreg[i][dd], kv.y, s4[i][1]);
                    s4[i][2] = fmaf(qreg[i][dd], kv.z, s4[i][2]);
                    s4[i][3] = fmaf(qreg[i][dd], kv.w, s4[i][3]);
                }
            }
        }

        // Online softmax update (row stats over 16 tx lanes)
#pragma unroll
        for (int i = 0; i < 4; i++) {
            float tm = fmaxf(fmaxf(s4[i][0], s4[i][1]), fmaxf(s4[i][2], s4[i][3]));
#pragma unroll
            for (int o = 8; o; o >>= 1) tm = fmaxf(tm, __shfl_xor_sync(0xffffffffu, tm, o));
            const float mnew = fmaxf(m_[i], tm);
            const float alpha = __expf(m_[i] - mnew);
            m_[i] = mnew;
            float rs = 0.f;
#pragma unroll
            for (int j = 0; j < 4; j++) {
                const float p = __expf(s4[i][j] - mnew);
                s4[i][j] = p;
                rs += p;
            }
#pragma unroll
            for (int o = 8; o; o >>= 1) rs += __shfl_xor_sync(0xffffffffu, rs, o);
            l_[i] = l_[i] * alpha + rs;
#pragma unroll
            for (int j = 0; j < 4; j++) acc[i][j] *= alpha;
        }

        __syncthreads();  // all threads done reading K^T
#pragma unroll
        for (int i = 0; i < 4; i++) {
            float4 pv;
            pv.x = s4[i][0]; pv.y = s4[i][1]; pv.z = s4[i][2]; pv.w = s4[i][3];
            *(float4*)&KP[(ty * 4 + i) * ATTN_S + tx * 4] = pv;  // P tile reuses K buf
        }
        __syncthreads();

        // acc += P @ V
#pragma unroll
        for (int c4 = 0; c4 < 64; c4 += 4) {
            float preg[4][4];
#pragma unroll
            for (int i = 0; i < 4; i++)
                *(float4*)preg[i] = *(const float4*)&KP[(ty * 4 + i) * ATTN_S + c4];
#pragma unroll
            for (int cc = 0; cc < 4; cc++) {
                const float4 vv = *(const float4*)&Vs[(c4 + cc) * ATTN_S + tx * 4];
#pragma unroll
                for (int i = 0; i < 4; i++) {
                    acc[i][0] = fmaf(preg[i][cc], vv.x, acc[i][0]);
                    acc[i][1] = fmaf(preg[i][cc], vv.y, acc[i][1]);
                    acc[i][2] = fmaf(preg[i][cc], vv.z, acc[i][2]);
                    acc[i][3] = fmaf(preg[i][cc], vv.w, acc[i][3]);
                }
            }
        }
    }

    // Write O (merged back to [m, h*64+d] layout)
#pragma unroll
    for (int i = 0; i < 4; i++) {
        const float inv = 1.0f / l_[i];
        float4 o4;
        o4.x = acc[i][0] * inv;
        o4.y = acc[i][1] * inv;
        o4.z = acc[i][2] * inv;
        o4.w = acc[i][3] * inv;
        const int gr = rowbase + ty * 4 + i;
        *(float4*)&ao[(size_t)gr * DMODEL + hoff + tx * 4] = o4;
    }
}

// ---------------------------------------------------------------------------
// Launcher
// Inputs (metadata order): x, ln1_scale, ln1_bias, qkv_w, out_w,
//                          ln2_scale, ln2_bias, fc1_w, fc1_b, fc2_w, fc2_b
// Output: float32 [4,2048,1024]
// ---------------------------------------------------------------------------
extern "C" void kernel_launch(void* const* d_in, const int* in_sizes, int n_in,
                              void* d_out, int out_size) {
    const float* x       = (const float*)d_in[0];
    const float* ln1_s   = (const float*)d_in[1];
    const float* ln1_b   = (const float*)d_in[2];
    const float* qkv_w   = (const float*)d_in[3];
    const float* out_w   = (const float*)d_in[4];
    const float* ln2_s   = (const float*)d_in[5];
    const float* ln2_b   = (const float*)d_in[6];
    const float* fc1_w   = (const float*)d_in[7];
    const float* fc1_b   = (const float*)d_in[8];
    const float* fc2_w   = (const float*)d_in[9];
    const float* fc2_b   = (const float*)d_in[10];
    float* out = (float*)d_out;

    float *ln_p, *qkv_p, *ao_p, *x1_p, *ff_p;
    cudaGetSymbolAddress((void**)&ln_p,  g_ln);
    cudaGetSymbolAddress((void**)&qkv_p, g_qkv);
    cudaGetSymbolAddress((void**)&ao_p,  g_ao);
    cudaGetSymbolAddress((void**)&x1_p,  g_x1);
    cudaGetSymbolAddress((void**)&ff_p,  g_ff);

    cudaFuncSetAttribute(attn_kernel, cudaFuncAttributeMaxDynamicSharedMemorySize,
                         ATTN_SMEM);

    // 1) LN1
    ln_kernel<<<MROWS, 256>>>(x, ln1_s, ln1_b, ln_p);

    // 2) QKV projection: [8192,1024] x [3072,1024]^T -> [8192,3072]
    gemm_nt<0><<<dim3(3 * DMODEL / 128, MROWS / 128), 256>>>(
        ln_p, qkv_w, qkv_p, MROWS, 3 * DMODEL, DMODEL, nullptr, nullptr);

    // 3) Attention
    attn_kernel<<<dim3(TSEQ / 64, NHEAD, BATCH), 256, ATTN_SMEM>>>(qkv_p, ao_p);

    // 4) Out projection + residual: x1 = x + ao @ out_w^T
    gemm_nt<1><<<dim3(DMODEL / 128, MROWS / 128), 256>>>(
        ao_p, out_w, x1_p, MROWS, DMODEL, DMODEL, nullptr, x);

    // 5) LN2
    ln_kernel<<<MROWS, 256>>>(x1_p, ln2_s, ln2_b, ln_p);

    // 6) FC1 + bias + exact GELU: [8192,1024] x [4096,1024]^T -> [8192,4096]
    gemm_nt<2><<<dim3(DFF / 128, MROWS / 128), 256>>>(
        ln_p, fc1_w, ff_p, MROWS, DFF, DMODEL, fc1_b, nullptr);

    // 7) FC2 + bias + residual: out = x1 + ff @ fc2_w^T + fc2_b
    gemm_nt<3><<<dim3(DMODEL / 128, MROWS / 128), 256>>>(
        ff_p, fc2_w, out, MROWS, DMODEL, DFF, fc2_b, x1_p);
}

// round 3
// speedup vs baseline: 1.6927x; 1.6927x over previous
#include <cuda_runtime.h>
#include <cuda_fp16.h>
#include <math.h>
#include <stdint.h>

// Problem constants
#define BATCH 4
#define TSEQ 2048
#define DMODEL 1024
#define NHEAD 16
#define DHEAD 64
#define DFF 4096
#define MROWS (BATCH * TSEQ)   // 8192

// ---------------------------------------------------------------------------
// Scratch (device globals; no runtime allocation allowed)
// ---------------------------------------------------------------------------
__device__ float  g_qkv[(size_t)MROWS * 3 * DMODEL];   // 96 MB fp32
__device__ float  g_x1[(size_t)MROWS * DMODEL];        // 32 MB fp32
__device__ __half g_a1_hi[(size_t)MROWS * DMODEL];     // activation split (LN out / attn out)
__device__ __half g_a1_lo[(size_t)MROWS * DMODEL];
__device__ __half g_ff_hi[(size_t)MROWS * DFF];
__device__ __half g_ff_lo[(size_t)MROWS * DFF];
__device__ __half g_wqkv_hi[(size_t)3 * DMODEL * DMODEL];
__device__ __half g_wqkv_lo[(size_t)3 * DMODEL * DMODEL];
__device__ __half g_wout_hi[(size_t)DMODEL * DMODEL];
__device__ __half g_wout_lo[(size_t)DMODEL * DMODEL];
__device__ __half g_wfc1_hi[(size_t)DFF * DMODEL];
__device__ __half g_wfc1_lo[(size_t)DFF * DMODEL];
__device__ __half g_wfc2_hi[(size_t)DMODEL * DFF];
__device__ __half g_wfc2_lo[(size_t)DMODEL * DFF];

// ---------------------------------------------------------------------------
// Helpers
// ---------------------------------------------------------------------------
__device__ __forceinline__ uint32_t smem_u32(const void* p) {
    uint32_t a;
    asm("{ .reg .u64 t; cvta.to.shared.u64 t, %1; cvt.u32.u64 %0, t; }"
        : "=r"(a) : "l"(p));
    return a;
}

#define LDSM_X4(d, a)                                                        \
    asm volatile("ldmatrix.sync.aligned.m8n8.x4.shared.b16 "                 \
                 "{%0,%1,%2,%3}, [%4];"                                      \
                 : "=r"((d)[0]), "=r"((d)[1]), "=r"((d)[2]), "=r"((d)[3])    \
                 : "r"(a))

#define MMA16816(c, a, b0, b1)                                               \
    asm volatile("mma.sync.aligned.m16n8k16.row.col.f32.f16.f16.f32 "        \
                 "{%0,%1,%2,%3},{%4,%5,%6,%7},{%8,%9},{%0,%1,%2,%3};"        \
                 : "+f"((c)[0]), "+f"((c)[1]), "+f"((c)[2]), "+f"((c)[3])    \
                 : "r"((a)[0]), "r"((a)[1]), "r"((a)[2]), "r"((a)[3]),       \
                   "r"(b0), "r"(b1))

#define CP_ASYNC16(s, g) \
    asm volatile("cp.async.cg.shared.global [%0], [%1], 16;" :: "r"(s), "l"(g))
#define CP_COMMIT() asm volatile("cp.async.commit_group;")
#define CP_WAIT1()  asm volatile("cp.async.wait_group 1;")

__device__ __forceinline__ float gelu_exact(float x) {
    return 0.5f * x * (1.0f + erff(x * 0.70710678118654752f));
}

__device__ __forceinline__ void split16(float v, __half& hi, __half& lo) {
    hi = __float2half_rn(v);
    lo = __float2half_rn(v - __half2float(hi));
}

// ---------------------------------------------------------------------------
// Weight split: fp32 -> (hi, lo) fp16, elementwise, vectorized by 4
// ---------------------------------------------------------------------------
__global__ __launch_bounds__(256)
void split_kernel(const float* __restrict__ in, __half* __restrict__ hi,
                  __half* __restrict__ lo, int n4) {
    const int i = blockIdx.x * 256 + threadIdx.x;
    if (i >= n4) return;
    const float4 v = ((const float4*)in)[i];
    __half hx, lx, hy, ly, hz, lz, hw, lw;
    split16(v.x, hx, lx); split16(v.y, hy, ly);
    split16(v.z, hz, lz); split16(v.w, hw, lw);
    ((__half2*)hi)[i * 2 + 0] = __halves2half2(hx, hy);
    ((__half2*)hi)[i * 2 + 1] = __halves2half2(hz, hw);
    ((__half2*)lo)[i * 2 + 0] = __halves2half2(lx, ly);
    ((__half2*)lo)[i * 2 + 1] = __halves2half2(lz, lw);
}

// ---------------------------------------------------------------------------
// LayerNorm: one block per row, 256 threads; outputs split fp16 hi/lo
// ---------------------------------------------------------------------------
__global__ __launch_bounds__(256)
void ln_kernel(const float* __restrict__ x, const float* __restrict__ sc,
               const float* __restrict__ bi,
               __half* __restrict__ yhi, __half* __restrict__ ylo) {
    const int row = blockIdx.x;
    const int t = threadIdx.x;
    const float4 v = *(const float4*)(x + (size_t)row * DMODEL + t * 4);
    float s = v.x + v.y + v.z + v.w;
    float s2 = v.x * v.x + v.y * v.y + v.z * v.z + v.w * v.w;
#pragma unroll
    for (int o = 16; o; o >>= 1) {
        s  += __shfl_xor_sync(0xffffffffu, s, o);
        s2 += __shfl_xor_sync(0xffffffffu, s2, o);
    }
    __shared__ float rs[8], rs2[8];
    if ((t & 31) == 0) { rs[t >> 5] = s; rs2[t >> 5] = s2; }
    __syncthreads();
    s = 0.f; s2 = 0.f;
#pragma unroll
    for (int i = 0; i < 8; i++) { s += rs[i]; s2 += rs2[i]; }
    const float mu = s * (1.0f / DMODEL);
    const float var = s2 * (1.0f / DMODEL) - mu * mu;
    const float r = rsqrtf(var + 1e-5f);
    const float4 g4 = *(const float4*)(sc + t * 4);
    const float4 b4 = *(const float4*)(bi + t * 4);
    float4 o4;
    o4.x = (v.x - mu) * r * g4.x + b4.x;
    o4.y = (v.y - mu) * r * g4.y + b4.y;
    o4.z = (v.z - mu) * r * g4.z + b4.z;
    o4.w = (v.w - mu) * r * g4.w + b4.w;
    __half hx, lx, hy, ly, hz, lz, hw, lw;
    split16(o4.x, hx, lx); split16(o4.y, hy, ly);
    split16(o4.z, hz, lz); split16(o4.w, hw, lw);
    const size_t off = (size_t)row * DMODEL + t * 4;
    ((__half2*)(yhi + off))[0] = __halves2half2(hx, hy);
    ((__half2*)(yhi + off))[1] = __halves2half2(hz, hw);
    ((__half2*)(ylo + off))[0] = __halves2half2(lx, ly);
    ((__half2*)(ylo + off))[1] = __halves2half2(lz, lw);
}

// ---------------------------------------------------------------------------
// HMMA split-fp16 GEMM: C[M,N] = A[M,K] @ W[N,K]^T with fp32-grade accuracy.
// A,W given as (hi,lo) fp16 pairs. acc += Ah*Wh + Ah*Wl + Al*Wh.
// CTA tile 128x128, BK=32, 8 warps (64x32 each), 3-stage cp.async pipeline.
//   EPI 0: none | 1: +res | 2: +bias,GELU | 3: +bias+res
//   SPLITOUT: write (hi,lo) fp16 pair instead of fp32.
// smem: 3 stages x 4 arrays (Ah, Al, Bh, Bl) x 128 rows x 80B = 122880 B
// ---------------------------------------------------------------------------
#define GH_STAGE 40960
#define GH_ARR   10240
#define GH_SMEM  (3 * GH_STAGE)

template <int EPI, bool SPLITOUT>
__global__ __launch_bounds__(256, 1)
void gemm_hmma(const __half* __restrict__ Ah, const __half* __restrict__ Al,
               const __half* __restrict__ Bh, const __half* __restrict__ Bl,
               float* __restrict__ C, __half* __restrict__ Ch,
               __half* __restrict__ Cl, int M, int N, int K,
               const float* __restrict__ bias, const float* __restrict__ res) {
    extern __shared__ char sm[];
    const uint32_t sb = smem_u32(sm);
    const int tid = threadIdx.x;
    const int lane = tid & 31, wid = tid >> 5;
    const int warp_m = wid >> 2, warp_n = wid & 3;
    const int bm = blockIdx.y * 128, bn = blockIdx.x * 128;
    const int NT = K >> 5;

    // stage loader: 4 arrays x 2 chunks per thread, 16B cp.async each
    auto load_stage = [&](int st, int kt) {
        const int k0 = kt * 32;
        const uint32_t so = sb + st * GH_STAGE;
#pragma unroll
        for (int arr = 0; arr < 4; arr++) {
            const __half* src = (arr == 0) ? Ah : (arr == 1) ? Al
                                : (arr == 2) ? Bh : Bl;
            const int base = (arr < 2) ? bm : bn;
#pragma unroll
            for (int i = 0; i < 2; i++) {
                const int idx = tid + i * 256;
                const int r = idx >> 2, kc = idx & 3;
                const void* g = src + (size_t)(base + r) * K + k0 + kc * 8;
                CP_ASYNC16(so + arr * GH_ARR + r * 80 + kc * 16, g);
            }
        }
    };

    load_stage(0, 0); CP_COMMIT();
    load_stage(1, 1); CP_COMMIT();

    float acc[4][4][4];
#pragma unroll
    for (int a = 0; a < 4; a++)
#pragma unroll
        for (int b = 0; b < 4; b++)
#pragma unroll
            for (int c = 0; c < 4; c++) acc[a][b][c] = 0.f;

    for (int kt = 0; kt < NT; kt++) {
        CP_WAIT1();
        __syncthreads();
        if (kt + 2 < NT) load_stage((kt + 2) % 3, kt + 2);
        CP_COMMIT();

        const uint32_t s0 = sb + (kt % 3) * GH_STAGE;
#pragma unroll
        for (int kh = 0; kh < 2; kh++) {
            uint32_t a_hi[4][4], a_lo[4][4], b_hi[2][4], b_lo[2][4];
#pragma unroll
            for (int mt = 0; mt < 4; mt++) {
                const int row = warp_m * 64 + mt * 16 + (lane & 15);
                const int chunk = kh * 2 + (lane >> 4);
                const uint32_t ad = s0 + row * 80 + chunk * 16;
                LDSM_X4(a_hi[mt], ad);
                LDSM_X4(a_lo[mt], ad + GH_ARR);
            }
#pragma unroll
            for (int nt = 0; nt < 2; nt++) {
                const int row = warp_n * 32 + nt * 16 + (lane & 7) + ((lane >> 4) << 3);
                const int chunk = kh * 2 + ((lane >> 3) & 1);
                const uint32_t ad = s0 + 2 * GH_ARR + row * 80 + chunk * 16;
                LDSM_X4(b_hi[nt], ad);
                LDSM_X4(b_lo[nt], ad + GH_ARR);
            }
            // hi*hi
#pragma unroll
            for (int mt = 0; mt < 4; mt++)
#pragma unroll
                for (int j = 0; j < 4; j++)
                    MMA16816(acc[mt][j], a_hi[mt],
                             b_hi[j >> 1][(j & 1) * 2], b_hi[j >> 1][(j & 1) * 2 + 1]);
            // hi*lo
#pragma unroll
            for (int mt = 0; mt < 4; mt++)
#pragma unroll
                for (int j = 0; j < 4; j++)
                    MMA16816(acc[mt][j], a_hi[mt],
                             b_lo[j >> 1][(j & 1) * 2], b_lo[j >> 1][(j & 1) * 2 + 1]);
            // lo*hi
#pragma unroll
            for (int mt = 0; mt < 4; mt++)
#pragma unroll
                for (int j = 0; j < 4; j++)
                    MMA16816(acc[mt][j], a_lo[mt],
                             b_hi[j >> 1][(j & 1) * 2], b_hi[j >> 1][(j & 1) * 2 + 1]);
        }
    }

    // Epilogue: lane holds (g = lane>>2, t = lane&3): rows g, g+8; cols t*2, t*2+1
    const int gq = lane >> 2, tq = lane & 3;
#pragma unroll
    for (int mt = 0; mt < 4; mt++) {
#pragma unroll
        for (int j = 0; j < 4; j++) {
            const int col = bn + warp_n * 32 + j * 8 + tq * 2;
            float2 bb = make_float2(0.f, 0.f);
            if (EPI == 2 || EPI == 3) bb = *(const float2*)&bias[col];
#pragma unroll
            for (int rr = 0; rr < 2; rr++) {
                const int row = bm + warp_m * 64 + mt * 16 + gq + rr * 8;
                float vx = acc[mt][j][rr * 2 + 0];
                float vy = acc[mt][j][rr * 2 + 1];
                if (EPI == 2 || EPI == 3) { vx += bb.x; vy += bb.y; }
                if (EPI == 2) { vx = gelu_exact(vx); vy = gelu_exact(vy); }
                if (EPI == 1 || EPI == 3) {
                    const float2 rv = *(const float2*)&res[(size_t)row * N + col];
                    vx += rv.x; vy += rv.y;
                }
                if (SPLITOUT) {
                    __half hx, lx, hy, ly;
                    split16(vx, hx, lx); split16(vy, hy, ly);
                    *(__half2*)&Ch[(size_t)row * N + col] = __halves2half2(hx, hy);
                    *(__half2*)&Cl[(size_t)row * N + col] = __halves2half2(lx, ly);
                } else {
                    *(float2*)&C[(size_t)row * N + col] = make_float2(vx, vy);
                }
            }
        }
    }
}

// ---------------------------------------------------------------------------
// Fused attention (flash-style, fp32): grid (T/64, H, B), 256 threads.
// Output written as split fp16 (hi, lo) for the following HMMA GEMM.
// ---------------------------------------------------------------------------
#define ATTN_S 68
#define ATTN_SMEM (3 * 64 * ATTN_S * 4)

__global__ __launch_bounds__(256)
void attn_kernel(const float* __restrict__ qkv,
                 __half* __restrict__ ao_hi, __half* __restrict__ ao_lo) {
    extern __shared__ float smf[];
    float* Qs = smf;
    float* KP = smf + 64 * ATTN_S;
    float* Vs = smf + 2 * 64 * ATTN_S;

    const int b = blockIdx.z, h = blockIdx.y, qt = blockIdx.x;
    const int tid = threadIdx.x;
    const int ty = tid >> 4, tx = tid & 15;
    const int hoff = h * DHEAD;
    const int rowbase = b * TSEQ + qt * 64;

#pragma unroll
    for (int p = 0; p < 4; p++) {
        const int idx = tid + p * 256;
        const int r = idx >> 4;
        const int c = (idx & 15) * 4;
        const float4 q = *(const float4*)&qkv[(size_t)(rowbase + r) * 3072 + hoff + c];
        float* dst = &Qs[r * ATTN_S + c];
        dst[0] = q.x * 0.125f; dst[1] = q.y * 0.125f;
        dst[2] = q.z * 0.125f; dst[3] = q.w * 0.125f;
    }

    float m_[4], l_[4], acc[4][4];
#pragma unroll
    for (int i = 0; i < 4; i++) {
        m_[i] = -3.0e38f; l_[i] = 0.f;
#pragma unroll
        for (int j = 0; j < 4; j++) acc[i][j] = 0.f;
    }

    for (int kt = 0; kt < TSEQ / 64; kt++) {
        __syncthreads();
        const int kvbase = b * TSEQ + kt * 64;
#pragma unroll
        for (int p = 0; p < 4; p++) {
            const int idx = tid + p * 256;
            const int r = idx >> 4;
            const int c = (idx & 15) * 4;
            const float* src = &qkv[(size_t)(kvbase + r) * 3072 + hoff + c];
            const float4 k4 = *(const float4*)(src + 1024);
            KP[(c + 0) * ATTN_S + r] = k4.x;
            KP[(c + 1) * ATTN_S + r] = k4.y;
            KP[(c + 2) * ATTN_S + r] = k4.z;
            KP[(c + 3) * ATTN_S + r] = k4.w;
            const float4 v4 = *(const float4*)(src + 2048);
            *(float4*)&Vs[r * ATTN_S + c] = v4;
        }
        __syncthreads();

        float s4[4][4];
#pragma unroll
        for (int i = 0; i < 4; i++)
#pragma unroll
            for (int j = 0; j < 4; j++) s4[i][j] = 0.f;

#pragma unroll
        for (int d4 = 0; d4 < 64; d4 += 4) {
            float qreg[4][4];
#pragma unroll
            for (int i = 0; i < 4; i++)
                *(float4*)qreg[i] = *(const float4*)&Qs[(ty * 4 + i) * ATTN_S + d4];
#pragma unroll
            for (int dd = 0; dd < 4; dd++) {
                const float4 kv = *(const float4*)&KP[(d4 + dd) * ATTN_S + tx * 4];
#pragma unroll
                for (int i = 0; i < 4; i++) {
                    s4[i][0] = fmaf(qreg[i][dd], kv.x, s4[i][0]);
                    s4[i][1] = fmaf(qreg[i][dd], kv.y, s4[i][1]);
                    s4[i][2] = fmaf(qreg[i][dd], kv.z, s4[i][2]);
                    s4[i][3] = fmaf(qreg[i][dd], kv.w, s4[i][3]);
                }
            }
        }

#pragma unroll
        for (int i = 0; i < 4; i++) {
            float tm = fmaxf(fmaxf(s4[i][0], s4[i][1]), fmaxf(s4[i][2], s4[i][3]));
#pragma unroll
            for (int o = 8; o; o >>= 1) tm = fmaxf(tm, __shfl_xor_sync(0xffffffffu, tm, o));
            const float mnew = fmaxf(m_[i], tm);
            const float alpha = __expf(m_[i] - mnew);
            m_[i] = mnew;
            float rs = 0.f;
#pragma unroll
            for (int j = 0; j < 4; j++) {
                const float p = __expf(s4[i][j] - mnew);
                s4[i][j] = p;
                rs += p;
            }
#pragma unroll
            for (int o = 8; o; o >>= 1) rs += __shfl_xor_sync(0xffffffffu, rs, o);
            l_[i] = l_[i] * alpha + rs;
#pragma unroll
            for (int j = 0; j < 4; j++) acc[i][j] *= alpha;
        }

        __syncthreads();
#pragma unroll
        for (int i = 0; i < 4; i++) {
            float4 pv;
            pv.x = s4[i][0]; pv.y = s4[i][1]; pv.z = s4[i][2]; pv.w = s4[i][3];
            *(float4*)&KP[(ty * 4 + i) * ATTN_S + tx * 4] = pv;
        }
        __syncthreads();

#pragma unroll
        for (int c4 = 0; c4 < 64; c4 += 4) {
            float preg[4][4];
#pragma unroll
            for (int i = 0; i < 4; i++)
                *(float4*)preg[i] = *(const float4*)&KP[(ty * 4 + i) * ATTN_S + c4];
#pragma unroll
            for (int cc = 0; cc < 4; cc++) {
                const float4 vv = *(const float4*)&Vs[(c4 + cc) * ATTN_S + tx * 4];
#pragma unroll
                for (int i = 0; i < 4; i++) {
                    acc[i][0] = fmaf(preg[i][cc], vv.x, acc[i][0]);
                    acc[i][1] = fmaf(preg[i][cc], vv.y, acc[i][1]);
                    acc[i][2] = fmaf(preg[i][cc], vv.z, acc[i][2]);
                    acc[i][3] = fmaf(preg[i][cc], vv.w, acc[i][3]);
                }
            }
        }
    }

#pragma unroll
    for (int i = 0; i < 4; i++) {
        const float inv = 1.0f / l_[i];
        const float ox = acc[i][0] * inv, oy = acc[i][1] * inv;
        const float oz = acc[i][2] * inv, ow = acc[i][3] * inv;
        __half hx, lx, hy, ly, hz, lz, hw, lw;
        split16(ox, hx, lx); split16(oy, hy, ly);
        split16(oz, hz, lz); split16(ow, hw, lw);
        const int gr = rowbase + ty * 4 + i;
        const size_t off = (size_t)gr * DMODEL + hoff + tx * 4;
        ((__half2*)(ao_hi + off))[0] = __halves2half2(hx, hy);
        ((__half2*)(ao_hi + off))[1] = __halves2half2(hz, hw);
        ((__half2*)(ao_lo + off))[0] = __halves2half2(lx, ly);
        ((__half2*)(ao_lo + off))[1] = __halves2half2(lz, lw);
    }
}

// ---------------------------------------------------------------------------
// Launcher
// Inputs: x, ln1_scale, ln1_bias, qkv_w, out_w, ln2_scale, ln2_bias,
//         fc1_w, fc1_b, fc2_w, fc2_b.  Output: float32 [4,2048,1024]
// ---------------------------------------------------------------------------
extern "C" void kernel_launch(void* const* d_in, const int* in_sizes, int n_in,
                              void* d_out, int out_size) {
    const float* x     = (const float*)d_in[0];
    const float* ln1_s = (const float*)d_in[1];
    const float* ln1_b = (const float*)d_in[2];
    const float* qkv_w = (const float*)d_in[3];
    const float* out_w = (const float*)d_in[4];
    const float* ln2_s = (const float*)d_in[5];
    const float* ln2_b = (const float*)d_in[6];
    const float* fc1_w = (const float*)d_in[7];
    const float* fc1_b = (const float*)d_in[8];
    const float* fc2_w = (const float*)d_in[9];
    const float* fc2_b = (const float*)d_in[10];
    float* out = (float*)d_out;

    float *qkv_p, *x1_p;
    __half *a1h, *a1l, *ffh, *ffl;
    __half *wqh, *wql, *woh, *wol, *w1h, *w1l, *w2h, *w2l;
    cudaGetSymbolAddress((void**)&qkv_p, g_qkv);
    cudaGetSymbolAddress((void**)&x1_p,  g_x1);
    cudaGetSymbolAddress((void**)&a1h, g_a1_hi);
    cudaGetSymbolAddress((void**)&a1l, g_a1_lo);
    cudaGetSymbolAddress((void**)&ffh, g_ff_hi);
    cudaGetSymbolAddress((void**)&ffl, g_ff_lo);
    cudaGetSymbolAddress((void**)&wqh, g_wqkv_hi);
    cudaGetSymbolAddress((void**)&wql, g_wqkv_lo);
    cudaGetSymbolAddress((void**)&woh, g_wout_hi);
    cudaGetSymbolAddress((void**)&wol, g_wout_lo);
    cudaGetSymbolAddress((void**)&w1h, g_wfc1_hi);
    cudaGetSymbolAddress((void**)&w1l, g_wfc1_lo);
    cudaGetSymbolAddress((void**)&w2h, g_wfc2_hi);
    cudaGetSymbolAddress((void**)&w2l, g_wfc2_lo);

    cudaFuncSetAttribute(attn_kernel, cudaFuncAttributeMaxDynamicSharedMemorySize, ATTN_SMEM);
    cudaFuncSetAttribute(gemm_hmma<0, false>, cudaFuncAttributeMaxDynamicSharedMemorySize, GH_SMEM);
    cudaFuncSetAttribute(gemm_hmma<1, false>, cudaFuncAttributeMaxDynamicSharedMemorySize, GH_SMEM);
    cudaFuncSetAttribute(gemm_hmma<2, true>,  cudaFuncAttributeMaxDynamicSharedMemorySize, GH_SMEM);
    cudaFuncSetAttribute(gemm_hmma<3, false>, cudaFuncAttributeMaxDynamicSharedMemorySize, GH_SMEM);

    // 0) Weight splits (fp32 -> hi/lo fp16)
    split_kernel<<<(3 * DMODEL * DMODEL / 4 + 255) / 256, 256>>>(qkv_w, wqh, wql, 3 * DMODEL * DMODEL / 4);
    split_kernel<<<(DMODEL * DMODEL / 4 + 255) / 256, 256>>>(out_w, woh, wol, DMODEL * DMODEL / 4);
    split_kernel<<<(DFF * DMODEL / 4 + 255) / 256, 256>>>(fc1_w, w1h, w1l, DFF * DMODEL / 4);
    split_kernel<<<(DMODEL * DFF / 4 + 255) / 256, 256>>>(fc2_w, w2h, w2l, DMODEL * DFF / 4);

    // 1) LN1 -> split activations
    ln_kernel<<<MROWS, 256>>>(x, ln1_s, ln1_b, a1h, a1l);

    // 2) QKV projection: [8192,1024] x [3072,1024]^T -> qkv fp32
    gemm_hmma<0, false><<<dim3(3 * DMODEL / 128, MROWS / 128), 256, GH_SMEM>>>(
        a1h, a1l, wqh, wql, qkv_p, nullptr, nullptr,
        MROWS, 3 * DMODEL, DMODEL, nullptr, nullptr);

    // 3) Attention -> split ao
    attn_kernel<<<dim3(TSEQ / 64, NHEAD, BATCH), 256, ATTN_SMEM>>>(qkv_p, a1h, a1l);

    // 4) Out projection + residual: x1 = x + ao @ out_w^T (fp32)
    gemm_hmma<1, false><<<dim3(DMODEL / 128, MROWS / 128), 256, GH_SMEM>>>(
        a1h, a1l, woh, wol, x1_p, nullptr, nullptr,
        MROWS, DMODEL, DMODEL, nullptr, x);

    // 5) LN2 -> split activations
    ln_kernel<<<MROWS, 256>>>(x1_p, ln2_s, ln2_b, a1h, a1l);

    // 6) FC1 + bias + GELU -> split ff
    gemm_hmma<2, true><<<dim3(DFF / 128, MROWS / 128), 256, GH_SMEM>>>(
        a1h, a1l, w1h, w1l, nullptr, ffh, ffl,
        MROWS, DFF, DMODEL, fc1_b, nullptr);

    // 7) FC2 + bias + residual -> out fp32
    gemm_hmma<3, false><<<dim3(DMODEL / 128, MROWS / 128), 256, GH_SMEM>>>(
        ffh, ffl, w2h, w2l, out, nullptr, nullptr,
        MROWS, DMODEL, DFF, fc2_b, x1_p);
}

// round 4
// speedup vs baseline: 2.8690x; 1.6949x over previous
#include <cuda_runtime.h>
#include <cuda_fp16.h>
#include <math.h>
#include <stdint.h>

// Problem constants
#define BATCH 4
#define TSEQ 2048
#define DMODEL 1024
#define NHEAD 16
#define DHEAD 64
#define DFF 4096
#define MROWS (BATCH * TSEQ)   // 8192

// ---------------------------------------------------------------------------
// Scratch (device globals; no runtime allocation allowed)
// ---------------------------------------------------------------------------
__device__ float  g_x1[(size_t)MROWS * DMODEL];        // 32 MB fp32
__device__ __half g_qkvh[(size_t)MROWS * 3 * DMODEL];  // 48 MB fp16 (single)
__device__ __half g_a1_hi[(size_t)MROWS * DMODEL];
__device__ __half g_a1_lo[(size_t)MROWS * DMODEL];
__device__ __half g_ff_hi[(size_t)MROWS * DFF];
__device__ __half g_ff_lo[(size_t)MROWS * DFF];
__device__ __half g_wqkv_hi[(size_t)3 * DMODEL * DMODEL];
__device__ __half g_wqkv_lo[(size_t)3 * DMODEL * DMODEL];
__device__ __half g_wout_hi[(size_t)DMODEL * DMODEL];
__device__ __half g_wout_lo[(size_t)DMODEL * DMODEL];
__device__ __half g_wfc1_hi[(size_t)DFF * DMODEL];
__device__ __half g_wfc1_lo[(size_t)DFF * DMODEL];
__device__ __half g_wfc2_hi[(size_t)DMODEL * DFF];
__device__ __half g_wfc2_lo[(size_t)DMODEL * DFF];

// ---------------------------------------------------------------------------
// Helpers
// ---------------------------------------------------------------------------
__device__ __forceinline__ uint32_t smem_u32(const void* p) {
    uint32_t a;
    asm("{ .reg .u64 t; cvta.to.shared.u64 t, %1; cvt.u32.u64 %0, t; }"
        : "=r"(a) : "l"(p));
    return a;
}

#define LDSM_X4(d, a)                                                        \
    asm volatile("ldmatrix.sync.aligned.m8n8.x4.shared.b16 "                 \
                 "{%0,%1,%2,%3}, [%4];"                                      \
                 : "=r"((d)[0]), "=r"((d)[1]), "=r"((d)[2]), "=r"((d)[3])    \
                 : "r"(a))

#define LDSM_X4_T(d, a)                                                      \
    asm volatile("ldmatrix.sync.aligned.m8n8.x4.trans.shared.b16 "           \
                 "{%0,%1,%2,%3}, [%4];"                                      \
                 : "=r"((d)[0]), "=r"((d)[1]), "=r"((d)[2]), "=r"((d)[3])    \
                 : "r"(a))

#define MMA16816(c, a, b0, b1)                                               \
    asm volatile("mma.sync.aligned.m16n8k16.row.col.f32.f16.f16.f32 "        \
                 "{%0,%1,%2,%3},{%4,%5,%6,%7},{%8,%9},{%0,%1,%2,%3};"        \
                 : "+f"((c)[0]), "+f"((c)[1]), "+f"((c)[2]), "+f"((c)[3])    \
                 : "r"((a)[0]), "r"((a)[1]), "r"((a)[2]), "r"((a)[3]),       \
                   "r"(b0), "r"(b1))

#define CP_ASYNC16(s, g) \
    asm volatile("cp.async.cg.shared.global [%0], [%1], 16;" :: "r"(s), "l"(g))
#define CP_COMMIT() asm volatile("cp.async.commit_group;")
#define CP_WAIT1()  asm volatile("cp.async.wait_group 1;")

__device__ __forceinline__ float gelu_exact(float x) {
    return 0.5f * x * (1.0f + erff(x * 0.70710678118654752f));
}

__device__ __forceinline__ void split16(float v, __half& hi, __half& lo) {
    hi = __float2half_rn(v);
    lo = __float2half_rn(v - __half2float(hi));
}

// ---------------------------------------------------------------------------
// Weight split: fp32 -> (hi, lo) fp16
// ---------------------------------------------------------------------------
__global__ __launch_bounds__(256)
void split_kernel(const float* __restrict__ in, __half* __restrict__ hi,
                  __half* __restrict__ lo, int n4) {
    const int i = blockIdx.x * 256 + threadIdx.x;
    if (i >= n4) return;
    const float4 v = ((const float4*)in)[i];
    __half hx, lx, hy, ly, hz, lz, hw, lw;
    split16(v.x, hx, lx); split16(v.y, hy, ly);
    split16(v.z, hz, lz); split16(v.w, hw, lw);
    ((__half2*)hi)[i * 2 + 0] = __halves2half2(hx, hy);
    ((__half2*)hi)[i * 2 + 1] = __halves2half2(hz, hw);
    ((__half2*)lo)[i * 2 + 0] = __halves2half2(lx, ly);
    ((__half2*)lo)[i * 2 + 1] = __halves2half2(lz, lw);
}

// ---------------------------------------------------------------------------
// LayerNorm -> split fp16 hi/lo
// ---------------------------------------------------------------------------
__global__ __launch_bounds__(256)
void ln_kernel(const float* __restrict__ x, const float* __restrict__ sc,
               const float* __restrict__ bi,
               __half* __restrict__ yhi, __half* __restrict__ ylo) {
    const int row = blockIdx.x;
    const int t = threadIdx.x;
    const float4 v = *(const float4*)(x + (size_t)row * DMODEL + t * 4);
    float s = v.x + v.y + v.z + v.w;
    float s2 = v.x * v.x + v.y * v.y + v.z * v.z + v.w * v.w;
#pragma unroll
    for (int o = 16; o; o >>= 1) {
        s  += __shfl_xor_sync(0xffffffffu, s, o);
        s2 += __shfl_xor_sync(0xffffffffu, s2, o);
    }
    __shared__ float rs[8], rs2[8];
    if ((t & 31) == 0) { rs[t >> 5] = s; rs2[t >> 5] = s2; }
    __syncthreads();
    s = 0.f; s2 = 0.f;
#pragma unroll
    for (int i = 0; i < 8; i++) { s += rs[i]; s2 += rs2[i]; }
    const float mu = s * (1.0f / DMODEL);
    const float var = s2 * (1.0f / DMODEL) - mu * mu;
    const float r = rsqrtf(var + 1e-5f);
    const float4 g4 = *(const float4*)(sc + t * 4);
    const float4 b4 = *(const float4*)(bi + t * 4);
    float4 o4;
    o4.x = (v.x - mu) * r * g4.x + b4.x;
    o4.y = (v.y - mu) * r * g4.y + b4.y;
    o4.z = (v.z - mu) * r * g4.z + b4.z;
    o4.w = (v.w - mu) * r * g4.w + b4.w;
    __half hx, lx, hy, ly, hz, lz, hw, lw;
    split16(o4.x, hx, lx); split16(o4.y, hy, ly);
    split16(o4.z, hz, lz); split16(o4.w, hw, lw);
    const size_t off = (size_t)row * DMODEL + t * 4;
    ((__half2*)(yhi + off))[0] = __halves2half2(hx, hy);
    ((__half2*)(yhi + off))[1] = __halves2half2(hz, hw);
    ((__half2*)(ylo + off))[0] = __halves2half2(lx, ly);
    ((__half2*)(ylo + off))[1] = __halves2half2(lz, lw);
}

// ---------------------------------------------------------------------------
// HMMA split-fp16 GEMM: C[M,N] = A[M,K] @ W[N,K]^T (3-term Markidis).
//   EPI 0: none | 1: +res | 2: +bias,GELU | 3: +bias+res
//   OUTMODE 0: fp32 C | 1: split (Ch,Cl) | 2: single fp16 Ch
// ---------------------------------------------------------------------------
#define GH_STAGE 40960
#define GH_ARR   10240
#define GH_SMEM  (3 * GH_STAGE)

template <int EPI, int OUTMODE>
__global__ __launch_bounds__(256, 1)
void gemm_hmma(const __half* __restrict__ Ah, const __half* __restrict__ Al,
               const __half* __restrict__ Bh, const __half* __restrict__ Bl,
               float* __restrict__ C, __half* __restrict__ Ch,
               __half* __restrict__ Cl, int M, int N, int K,
               const float* __restrict__ bias, const float* __restrict__ res) {
    extern __shared__ char sm[];
    const uint32_t sb = smem_u32(sm);
    const int tid = threadIdx.x;
    const int lane = tid & 31, wid = tid >> 5;
    const int warp_m = wid >> 2, warp_n = wid & 3;
    const int bm = blockIdx.y * 128, bn = blockIdx.x * 128;
    const int NT = K >> 5;

    auto load_stage = [&](int st, int kt) {
        const int k0 = kt * 32;
        const uint32_t so = sb + st * GH_STAGE;
#pragma unroll
        for (int arr = 0; arr < 4; arr++) {
            const __half* src = (arr == 0) ? Ah : (arr == 1) ? Al
                                : (arr == 2) ? Bh : Bl;
            const int base = (arr < 2) ? bm : bn;
#pragma unroll
            for (int i = 0; i < 2; i++) {
                const int idx = tid + i * 256;
                const int r = idx >> 2, kc = idx & 3;
                const void* g = src + (size_t)(base + r) * K + k0 + kc * 8;
                CP_ASYNC16(so + arr * GH_ARR + r * 80 + kc * 16, g);
            }
        }
    };

    load_stage(0, 0); CP_COMMIT();
    load_stage(1, 1); CP_COMMIT();

    float acc[4][4][4];
#pragma unroll
    for (int a = 0; a < 4; a++)
#pragma unroll
        for (int b = 0; b < 4; b++)
#pragma unroll
            for (int c = 0; c < 4; c++) acc[a][b][c] = 0.f;

    for (int kt = 0; kt < NT; kt++) {
        CP_WAIT1();
        __syncthreads();
        if (kt + 2 < NT) load_stage((kt + 2) % 3, kt + 2);
        CP_COMMIT();

        const uint32_t s0 = sb + (kt % 3) * GH_STAGE;
#pragma unroll
        for (int kh = 0; kh < 2; kh++) {
            uint32_t a_hi[4][4], a_lo[4][4], b_hi[2][4], b_lo[2][4];
#pragma unroll
            for (int mt = 0; mt < 4; mt++) {
                const int row = warp_m * 64 + mt * 16 + (lane & 15);
                const int chunk = kh * 2 + (lane >> 4);
                const uint32_t ad = s0 + row * 80 + chunk * 16;
                LDSM_X4(a_hi[mt], ad);
                LDSM_X4(a_lo[mt], ad + GH_ARR);
            }
#pragma unroll
            for (int nt = 0; nt < 2; nt++) {
                const int row = warp_n * 32 + nt * 16 + (lane & 7) + ((lane >> 4) << 3);
                const int chunk = kh * 2 + ((lane >> 3) & 1);
                const uint32_t ad = s0 + 2 * GH_ARR + row * 80 + chunk * 16;
                LDSM_X4(b_hi[nt], ad);
                LDSM_X4(b_lo[nt], ad + GH_ARR);
            }
#pragma unroll
            for (int mt = 0; mt < 4; mt++)
#pragma unroll
                for (int j = 0; j < 4; j++)
                    MMA16816(acc[mt][j], a_hi[mt],
                             b_hi[j >> 1][(j & 1) * 2], b_hi[j >> 1][(j & 1) * 2 + 1]);
#pragma unroll
            for (int mt = 0; mt < 4; mt++)
#pragma unroll
                for (int j = 0; j < 4; j++)
                    MMA16816(acc[mt][j], a_hi[mt],
                             b_lo[j >> 1][(j & 1) * 2], b_lo[j >> 1][(j & 1) * 2 + 1]);
#pragma unroll
            for (int mt = 0; mt < 4; mt++)
#pragma unroll
                for (int j = 0; j < 4; j++)
                    MMA16816(acc[mt][j], a_lo[mt],
                             b_hi[j >> 1][(j & 1) * 2], b_hi[j >> 1][(j & 1) * 2 + 1]);
        }
    }

    const int gq = lane >> 2, tq = lane & 3;
#pragma unroll
    for (int mt = 0; mt < 4; mt++) {
#pragma unroll
        for (int j = 0; j < 4; j++) {
            const int col = bn + warp_n * 32 + j * 8 + tq * 2;
            float2 bb = make_float2(0.f, 0.f);
            if (EPI == 2 || EPI == 3) bb = *(const float2*)&bias[col];
#pragma unroll
            for (int rr = 0; rr < 2; rr++) {
                const int row = bm + warp_m * 64 + mt * 16 + gq + rr * 8;
                float vx = acc[mt][j][rr * 2 + 0];
                float vy = acc[mt][j][rr * 2 + 1];
                if (EPI == 2 || EPI == 3) { vx += bb.x; vy += bb.y; }
                if (EPI == 2) { vx = gelu_exact(vx); vy = gelu_exact(vy); }
                if (EPI == 1 || EPI == 3) {
                    const float2 rv = *(const float2*)&res[(size_t)row * N + col];
                    vx += rv.x; vy += rv.y;
                }
                if (OUTMODE == 1) {
                    __half hx, lx, hy, ly;
                    split16(vx, hx, lx); split16(vy, hy, ly);
                    *(__half2*)&Ch[(size_t)row * N + col] = __halves2half2(hx, hy);
                    *(__half2*)&Cl[(size_t)row * N + col] = __halves2half2(lx, ly);
                } else if (OUTMODE == 2) {
                    *(__half2*)&Ch[(size_t)row * N + col] = __floats2half2_rn(vx, vy);
                } else {
                    *(float2*)&C[(size_t)row * N + col] = make_float2(vx, vy);
                }
            }
        }
    }
}

// ---------------------------------------------------------------------------
// HMMA flash attention. Grid (T/64, H, B), 128 threads = 4 warps.
// qkv fp16 [row][3072]: Q at hoff, K at 1024+hoff, V at 2048+hoff.
// Warp w: 16 q-rows (w*16..). K/V tiles 64x64 fp16, cp.async double buffer.
// Output: split fp16 (hi,lo) at [row][hoff+d].
// ---------------------------------------------------------------------------
#define AQ_S 72                       // smem row stride in halfs (144 B)
#define ATT_Q     0
#define ATT_K(s)  (4608 + (s) * 4608)
#define ATT_V(s)  (13824 + (s) * 4608)
#define ATT_SMEM  (23040 * 2)         // 46080 B

__global__ __launch_bounds__(128, 3)
void attn_hmma(const __half* __restrict__ qkv,
               __half* __restrict__ ao_hi, __half* __restrict__ ao_lo) {
    extern __shared__ __half sh[];
    const uint32_t sb = smem_u32(sh);
    const int tid = threadIdx.x;
    const int lane = tid & 31, w = tid >> 5;
    const int b = blockIdx.z, h = blockIdx.y, qt = blockIdx.x;
    const int hoff = h * DHEAD;
    const int rowbase = b * TSEQ + qt * 64;

    // Load Q tile (64 rows x 64 halfs), plain vectorized loads
#pragma unroll
    for (int p = 0; p < 4; p++) {
        const int idx = tid + p * 128;
        const int r = idx >> 3, c8 = idx & 7;
        *(uint4*)(sh + ATT_Q + r * AQ_S + c8 * 8) =
            *(const uint4*)(qkv + (size_t)(rowbase + r) * 3072 + hoff + c8 * 8);
    }

    auto load_kv = [&](int st, int kt) {
        const int kvbase = b * TSEQ + kt * 64;
#pragma unroll
        for (int p = 0; p < 4; p++) {
            const int idx = tid + p * 128;
            const int r = idx >> 3, c8 = idx & 7;
            const __half* gk = qkv + (size_t)(kvbase + r) * 3072 + 1024 + hoff + c8 * 8;
            CP_ASYNC16(sb + 2 * (ATT_K(st) + r * AQ_S + c8 * 8), gk);
            CP_ASYNC16(sb + 2 * (ATT_V(st) + r * AQ_S + c8 * 8), gk + 1024);
        }
    };

    load_kv(0, 0); CP_COMMIT();
    __syncthreads();

    // Preload Q A-fragments (rows w*16.., 4 k-steps of 16)
    uint32_t qa[4][4];
    const int m0 = w * 16;
#pragma unroll
    for (int kk = 0; kk < 4; kk++) {
        const uint32_t ad = sb + 2 * (ATT_Q + (m0 + (lane & 15)) * AQ_S +
                                      kk * 16 + (lane >> 4) * 8);
        LDSM_X4(qa[kk], ad);
    }

    float m_[2] = {-1e30f, -1e30f}, l_[2] = {0.f, 0.f};
    float o[8][4];
#pragma unroll
    for (int n = 0; n < 8; n++)
#pragma unroll
        for (int j = 0; j < 4; j++) o[n][j] = 0.f;

    const int NT = TSEQ / 64;
    for (int kt = 0; kt < NT; kt++) {
        __syncthreads();                 // stage reuse guard
        if (kt + 1 < NT) load_kv((kt + 1) & 1, kt + 1);
        CP_COMMIT();
        CP_WAIT1();
        __syncthreads();                 // visibility of stage kt
        const int s = kt & 1;

        // ---- S = Q K^T (64-key tile), fp32 accum ----
        float c[8][4];
#pragma unroll
        for (int n = 0; n < 8; n++)
#pragma unroll
            for (int j = 0; j < 4; j++) c[n][j] = 0.f;

#pragma unroll
        for (int kk2 = 0; kk2 < 2; kk2++) {
#pragma unroll
            for (int n = 0; n < 8; n++) {
                uint32_t bf[4];
                const uint32_t ad = sb + 2 * (ATT_K(s) + (n * 8 + (lane & 7)) * AQ_S +
                                              kk2 * 32 + (lane >> 3) * 8);
                LDSM_X4(bf, ad);
                MMA16816(c[n], qa[2 * kk2], bf[0], bf[1]);
                MMA16816(c[n], qa[2 * kk2 + 1], bf[2], bf[3]);
            }
        }

        // ---- online softmax (rows r0=lane>>2, r1=r0+8; cols over 4 lanes) ----
        float tm0 = -1e30f, tm1 = -1e30f;
#pragma unroll
        for (int n = 0; n < 8; n++) {
            tm0 = fmaxf(tm0, fmaxf(c[n][0], c[n][1]));
            tm1 = fmaxf(tm1, fmaxf(c[n][2], c[n][3]));
        }
#pragma unroll
        for (int ofs = 1; ofs <= 2; ofs <<= 1) {
            tm0 = fmaxf(tm0, __shfl_xor_sync(0xffffffffu, tm0, ofs));
            tm1 = fmaxf(tm1, __shfl_xor_sync(0xffffffffu, tm1, ofs));
        }
        tm0 *= 0.125f; tm1 *= 0.125f;
        const float mn0 = fmaxf(m_[0], tm0), mn1 = fmaxf(m_[1], tm1);
        const float al0 = __expf(m_[0] - mn0), al1 = __expf(m_[1] - mn1);
        m_[0] = mn0; m_[1] = mn1;

        uint32_t u01[8], u23[8];
        float rs0 = 0.f, rs1 = 0.f;
#pragma unroll
        for (int n = 0; n < 8; n++) {
            const float p0 = __expf(c[n][0] * 0.125f - mn0);
            const float p1 = __expf(c[n][1] * 0.125f - mn0);
            const float p2 = __expf(c[n][2] * 0.125f - mn1);
            const float p3 = __expf(c[n][3] * 0.125f - mn1);
            rs0 += p0 + p1; rs1 += p2 + p3;
            const __half2 h01 = __floats2half2_rn(p0, p1);
            const __half2 h23 = __floats2half2_rn(p2, p3);
            u01[n] = *(const uint32_t*)&h01;
            u23[n] = *(const uint32_t*)&h23;
        }
#pragma unroll
        for (int ofs = 1; ofs <= 2; ofs <<= 1) {
            rs0 += __shfl_xor_sync(0xffffffffu, rs0, ofs);
            rs1 += __shfl_xor_sync(0xffffffffu, rs1, ofs);
        }
        l_[0] = l_[0] * al0 + rs0;
        l_[1] = l_[1] * al1 + rs1;
#pragma unroll
        for (int n = 0; n < 8; n++) {
            o[n][0] *= al0; o[n][1] *= al0;
            o[n][2] *= al1; o[n][3] *= al1;
        }

        // ---- O += P V ----
#pragma unroll
        for (int kk = 0; kk < 4; kk++) {
            uint32_t au[4] = {u01[2 * kk], u23[2 * kk], u01[2 * kk + 1], u23[2 * kk + 1]};
#pragma unroll
            for (int n2 = 0; n2 < 4; n2++) {
                uint32_t bf[4];
                const uint32_t ad = sb + 2 * (ATT_V(s) + (kk * 16 + (lane & 15)) * AQ_S +
                                              n2 * 16 + (lane >> 4) * 8);
                LDSM_X4_T(bf, ad);
                MMA16816(o[2 * n2], au, bf[0], bf[1]);
                MMA16816(o[2 * n2 + 1], au, bf[2], bf[3]);
            }
        }
    }

    // ---- epilogue: O/l -> split fp16 ----
    const float inv0 = 1.0f / l_[0], inv1 = 1.0f / l_[1];
    const int r0 = lane >> 2, tq = lane & 3;
    const int grow0 = rowbase + m0 + r0, grow1 = grow0 + 8;
#pragma unroll
    for (int n = 0; n < 8; n++) {
        const int col = hoff + n * 8 + tq * 2;
        float v0 = o[n][0] * inv0, v1 = o[n][1] * inv0;
        float v2 = o[n][2] * inv1, v3 = o[n][3] * inv1;
        __half h0, l0, h1, l1, h2, l2, h3, l3;
        split16(v0, h0, l0); split16(v1, h1, l1);
        split16(v2, h2, l2); split16(v3, h3, l3);
        *(__half2*)&ao_hi[(size_t)grow0 * DMODEL + col] = __halves2half2(h0, h1);
        *(__half2*)&ao_lo[(size_t)grow0 * DMODEL + col] = __halves2half2(l0, l1);
        *(__half2*)&ao_hi[(size_t)grow1 * DMODEL + col] = __halves2half2(h2, h3);
        *(__half2*)&ao_lo[(size_t)grow1 * DMODEL + col] = __halves2half2(l2, l3);
    }
}

// ---------------------------------------------------------------------------
// Launcher
// ---------------------------------------------------------------------------
extern "C" void kernel_launch(void* const* d_in, const int* in_sizes, int n_in,
                              void* d_out, int out_size) {
    const float* x     = (const float*)d_in[0];
    const float* ln1_s = (const float*)d_in[1];
    const float* ln1_b = (const float*)d_in[2];
    const float* qkv_w = (const float*)d_in[3];
    const float* out_w = (const float*)d_in[4];
    const float* ln2_s = (const float*)d_in[5];
    const float* ln2_b = (const float*)d_in[6];
    const float* fc1_w = (const float*)d_in[7];
    const float* fc1_b = (const float*)d_in[8];
    const float* fc2_w = (const float*)d_in[9];
    const float* fc2_b = (const float*)d_in[10];
    float* out = (float*)d_out;

    float *x1_p;
    __half *qkvh, *a1h, *a1l, *ffh, *ffl;
    __half *wqh, *wql, *woh, *wol, *w1h, *w1l, *w2h, *w2l;
    cudaGetSymbolAddress((void**)&x1_p,  g_x1);
    cudaGetSymbolAddress((void**)&qkvh, g_qkvh);
    cudaGetSymbolAddress((void**)&a1h, g_a1_hi);
    cudaGetSymbolAddress((void**)&a1l, g_a1_lo);
    cudaGetSymbolAddress((void**)&ffh, g_ff_hi);
    cudaGetSymbolAddress((void**)&ffl, g_ff_lo);
    cudaGetSymbolAddress((void**)&wqh, g_wqkv_hi);
    cudaGetSymbolAddress((void**)&wql, g_wqkv_lo);
    cudaGetSymbolAddress((void**)&woh, g_wout_hi);
    cudaGetSymbolAddress((void**)&wol, g_wout_lo);
    cudaGetSymbolAddress((void**)&w1h, g_wfc1_hi);
    cudaGetSymbolAddress((void**)&w1l, g_wfc1_lo);
    cudaGetSymbolAddress((void**)&w2h, g_wfc2_hi);
    cudaGetSymbolAddress((void**)&w2l, g_wfc2_lo);

    cudaFuncSetAttribute(gemm_hmma<0, 2>, cudaFuncAttributeMaxDynamicSharedMemorySize, GH_SMEM);
    cudaFuncSetAttribute(gemm_hmma<1, 0>, cudaFuncAttributeMaxDynamicSharedMemorySize, GH_SMEM);
    cudaFuncSetAttribute(gemm_hmma<2, 1>, cudaFuncAttributeMaxDynamicSharedMemorySize, GH_SMEM);
    cudaFuncSetAttribute(gemm_hmma<3, 0>, cudaFuncAttributeMaxDynamicSharedMemorySize, GH_SMEM);

    // 0) Weight splits
    split_kernel<<<3 * DMODEL * DMODEL / 4 / 256, 256>>>(qkv_w, wqh, wql, 3 * DMODEL * DMODEL / 4);
    split_kernel<<<DMODEL * DMODEL / 4 / 256, 256>>>(out_w, woh, wol, DMODEL * DMODEL / 4);
    split_kernel<<<DFF * DMODEL / 4 / 256, 256>>>(fc1_w, w1h, w1l, DFF * DMODEL / 4);
    split_kernel<<<DMODEL * DFF / 4 / 256, 256>>>(fc2_w, w2h, w2l, DMODEL * DFF / 4);

    // 1) LN1 -> split activations
    ln_kernel<<<MROWS, 256>>>(x, ln1_s, ln1_b, a1h, a1l);

    // 2) QKV projection -> single fp16
    gemm_hmma<0, 2><<<dim3(3 * DMODEL / 128, MROWS / 128), 256, GH_SMEM>>>(
        a1h, a1l, wqh, wql, nullptr, qkvh, nullptr,
        MROWS, 3 * DMODEL, DMODEL, nullptr, nullptr);

    // 3) HMMA flash attention -> split ao
    attn_hmma<<<dim3(TSEQ / 64, NHEAD, BATCH), 128, ATT_SMEM>>>(qkvh, a1h, a1l);

    // 4) Out projection + residual -> x1 fp32
    gemm_hmma<1, 0><<<dim3(DMODEL / 128, MROWS / 128), 256, GH_SMEM>>>(
        a1h, a1l, woh, wol, x1_p, nullptr, nullptr,
        MROWS, DMODEL, DMODEL, nullptr, x);

    // 5) LN2 -> split activations
    ln_kernel<<<MROWS, 256>>>(x1_p, ln2_s, ln2_b, a1h, a1l);

    // 6) FC1 + bias + GELU -> split ff
    gemm_hmma<2, 1><<<dim3(DFF / 128, MROWS / 128), 256, GH_SMEM>>>(
        a1h, a1l, w1h, w1l, nullptr, ffh, ffl,
        MROWS, DFF, DMODEL, fc1_b, nullptr);

    // 7) FC2 + bias + residual -> out fp32
    gemm_hmma<3, 0><<<dim3(DMODEL / 128, MROWS / 128), 256, GH_SMEM>>>(
        ffh, ffl, w2h, w2l, out, nullptr, nullptr,
        MROWS, DMODEL, DFF, fc2_b, x1_p);
}

// round 5
// speedup vs baseline: 3.8159x; 1.3300x over previous
#include <cuda_runtime.h>
#include <cuda_fp16.h>
#include <math.h>
#include <stdint.h>

// Problem constants
#define BATCH 4
#define TSEQ 2048
#define DMODEL 1024
#define NHEAD 16
#define DHEAD 64
#define DFF 4096
#define MROWS (BATCH * TSEQ)   // 8192

// ---------------------------------------------------------------------------
// Scratch (device globals; no runtime allocation allowed)
// ---------------------------------------------------------------------------
__device__ float  g_x1[(size_t)MROWS * DMODEL];        // 32 MB fp32
__device__ __half g_qkvh[(size_t)MROWS * 3 * DMODEL];  // 48 MB fp16
__device__ __half g_act[(size_t)MROWS * DMODEL];       // activations fp16
__device__ __half g_ff[(size_t)MROWS * DFF];           // GELU out fp16
__device__ __half g_wqkv_hi[(size_t)3 * DMODEL * DMODEL];
__device__ __half g_wqkv_lo[(size_t)3 * DMODEL * DMODEL];
__device__ __half g_wout_hi[(size_t)DMODEL * DMODEL];
__device__ __half g_wout_lo[(size_t)DMODEL * DMODEL];
__device__ __half g_wfc1_hi[(size_t)DFF * DMODEL];
__device__ __half g_wfc1_lo[(size_t)DFF * DMODEL];
__device__ __half g_wfc2_hi[(size_t)DMODEL * DFF];
__device__ __half g_wfc2_lo[(size_t)DMODEL * DFF];

// ---------------------------------------------------------------------------
// Helpers
// ---------------------------------------------------------------------------
__device__ __forceinline__ uint32_t smem_u32(const void* p) {
    uint32_t a;
    asm("{ .reg .u64 t; cvta.to.shared.u64 t, %1; cvt.u32.u64 %0, t; }"
        : "=r"(a) : "l"(p));
    return a;
}

#define LDSM_X4(d, a)                                                        \
    asm volatile("ldmatrix.sync.aligned.m8n8.x4.shared.b16 "                 \
                 "{%0,%1,%2,%3}, [%4];"                                      \
                 : "=r"((d)[0]), "=r"((d)[1]), "=r"((d)[2]), "=r"((d)[3])    \
                 : "r"(a))

#define LDSM_X4_T(d, a)                                                      \
    asm volatile("ldmatrix.sync.aligned.m8n8.x4.trans.shared.b16 "           \
                 "{%0,%1,%2,%3}, [%4];"                                      \
                 : "=r"((d)[0]), "=r"((d)[1]), "=r"((d)[2]), "=r"((d)[3])    \
                 : "r"(a))

#define MMA16816(c, a, b0, b1)                                               \
    asm volatile("mma.sync.aligned.m16n8k16.row.col.f32.f16.f16.f32 "        \
                 "{%0,%1,%2,%3},{%4,%5,%6,%7},{%8,%9},{%0,%1,%2,%3};"        \
                 : "+f"((c)[0]), "+f"((c)[1]), "+f"((c)[2]), "+f"((c)[3])    \
                 : "r"((a)[0]), "r"((a)[1]), "r"((a)[2]), "r"((a)[3]),       \
                   "r"(b0), "r"(b1))

#define CP_ASYNC16(s, g) \
    asm volatile("cp.async.cg.shared.global [%0], [%1], 16;" :: "r"(s), "l"(g))
#define CP_COMMIT() asm volatile("cp.async.commit_group;")
#define CP_WAIT1()  asm volatile("cp.async.wait_group 1;")

__device__ __forceinline__ float gelu_exact(float x) {
    return 0.5f * x * (1.0f + erff(x * 0.70710678118654752f));
}

__device__ __forceinline__ void split16(float v, __half& hi, __half& lo) {
    hi = __float2half_rn(v);
    lo = __float2half_rn(v - __half2float(hi));
}

// ---------------------------------------------------------------------------
// Weight split: fp32 -> (hi, lo) fp16
// ---------------------------------------------------------------------------
__global__ __launch_bounds__(256)
void split_kernel(const float* __restrict__ in, __half* __restrict__ hi,
                  __half* __restrict__ lo, int n4) {
    const int i = blockIdx.x * 256 + threadIdx.x;
    if (i >= n4) return;
    const float4 v = ((const float4*)in)[i];
    __half hx, lx, hy, ly, hz, lz, hw, lw;
    split16(v.x, hx, lx); split16(v.y, hy, ly);
    split16(v.z, hz, lz); split16(v.w, hw, lw);
    ((__half2*)hi)[i * 2 + 0] = __halves2half2(hx, hy);
    ((__half2*)hi)[i * 2 + 1] = __halves2half2(hz, hw);
    ((__half2*)lo)[i * 2 + 0] = __halves2half2(lx, ly);
    ((__half2*)lo)[i * 2 + 1] = __halves2half2(lz, lw);
}

// ---------------------------------------------------------------------------
// LayerNorm -> single fp16
// ---------------------------------------------------------------------------
__global__ __launch_bounds__(256)
void ln_kernel(const float* __restrict__ x, const float* __restrict__ sc,
               const float* __restrict__ bi, __half* __restrict__ y) {
    const int row = blockIdx.x;
    const int t = threadIdx.x;
    const float4 v = *(const float4*)(x + (size_t)row * DMODEL + t * 4);
    float s = v.x + v.y + v.z + v.w;
    float s2 = v.x * v.x + v.y * v.y + v.z * v.z + v.w * v.w;
#pragma unroll
    for (int o = 16; o; o >>= 1) {
        s  += __shfl_xor_sync(0xffffffffu, s, o);
        s2 += __shfl_xor_sync(0xffffffffu, s2, o);
    }
    __shared__ float rs[8], rs2[8];
    if ((t & 31) == 0) { rs[t >> 5] = s; rs2[t >> 5] = s2; }
    __syncthreads();
    s = 0.f; s2 = 0.f;
#pragma unroll
    for (int i = 0; i < 8; i++) { s += rs[i]; s2 += rs2[i]; }
    const float mu = s * (1.0f / DMODEL);
    const float var = s2 * (1.0f / DMODEL) - mu * mu;
    const float r = rsqrtf(var + 1e-5f);
    const float4 g4 = *(const float4*)(sc + t * 4);
    const float4 b4 = *(const float4*)(bi + t * 4);
    float4 o4;
    o4.x = (v.x - mu) * r * g4.x + b4.x;
    o4.y = (v.y - mu) * r * g4.y + b4.y;
    o4.z = (v.z - mu) * r * g4.z + b4.z;
    o4.w = (v.w - mu) * r * g4.w + b4.w;
    const size_t off = (size_t)row * DMODEL + t * 4;
    ((__half2*)(y + off))[0] = __floats2half2_rn(o4.x, o4.y);
    ((__half2*)(y + off))[1] = __floats2half2_rn(o4.z, o4.w);
}

// ---------------------------------------------------------------------------
// HMMA 2-term GEMM: C[M,N] = A[M,K] @ (Wh + Wl)[N,K]^T
// A single fp16 (quantized activations), W split hi/lo fp16 (exact fp32 weight).
//   EPI 0: none | 1: +res | 2: +bias,GELU | 3: +bias+res
//   OUTMODE 0: fp32 C | 2: single fp16 Ch
// CTA tile 128x128, BK=32, 8 warps (64x32 each), 3-stage cp.async pipeline.
// smem: 3 stages x 3 arrays (A, Bh, Bl) x 128 rows x 80B = 92160 B
// ---------------------------------------------------------------------------
#define GH_ARR   10240
#define GH_STAGE (3 * GH_ARR)
#define GH_SMEM  (3 * GH_STAGE)

template <int EPI, int OUTMODE>
__global__ __launch_bounds__(256, 1)
void gemm_hmma(const __half* __restrict__ Ah, const __half* __restrict__ Bh,
               const __half* __restrict__ Bl,
               float* __restrict__ C, __half* __restrict__ Ch,
               int M, int N, int K,
               const float* __restrict__ bias, const float* __restrict__ res) {
    extern __shared__ char sm[];
    const uint32_t sb = smem_u32(sm);
    const int tid = threadIdx.x;
    const int lane = tid & 31, wid = tid >> 5;
    const int warp_m = wid >> 2, warp_n = wid & 3;
    const int bm = blockIdx.y * 128, bn = blockIdx.x * 128;
    const int NT = K >> 5;

    auto load_stage = [&](int st, int kt) {
        const int k0 = kt * 32;
        const uint32_t so = sb + st * GH_STAGE;
#pragma unroll
        for (int arr = 0; arr < 3; arr++) {
            const __half* src = (arr == 0) ? Ah : (arr == 1) ? Bh : Bl;
            const int base = (arr == 0) ? bm : bn;
#pragma unroll
            for (int i = 0; i < 2; i++) {
                const int idx = tid + i * 256;
                const int r = idx >> 2, kc = idx & 3;
                const void* g = src + (size_t)(base + r) * K + k0 + kc * 8;
                CP_ASYNC16(so + arr * GH_ARR + r * 80 + kc * 16, g);
            }
        }
    };

    load_stage(0, 0); CP_COMMIT();
    load_stage(1, 1); CP_COMMIT();

    float acc[4][4][4];
#pragma unroll
    for (int a = 0; a < 4; a++)
#pragma unroll
        for (int b = 0; b < 4; b++)
#pragma unroll
            for (int c = 0; c < 4; c++) acc[a][b][c] = 0.f;

    for (int kt = 0; kt < NT; kt++) {
        CP_WAIT1();
        __syncthreads();
        if (kt + 2 < NT) load_stage((kt + 2) % 3, kt + 2);
        CP_COMMIT();

        const uint32_t s0 = sb + (kt % 3) * GH_STAGE;
#pragma unroll
        for (int kh = 0; kh < 2; kh++) {
            uint32_t a_f[4][4], b_hi[2][4], b_lo[2][4];
#pragma unroll
            for (int mt = 0; mt < 4; mt++) {
                const int row = warp_m * 64 + mt * 16 + (lane & 15);
                const int chunk = kh * 2 + (lane >> 4);
                LDSM_X4(a_f[mt], s0 + row * 80 + chunk * 16);
            }
#pragma unroll
            for (int nt = 0; nt < 2; nt++) {
                const int row = warp_n * 32 + nt * 16 + (lane & 7) + ((lane >> 4) << 3);
                const int chunk = kh * 2 + ((lane >> 3) & 1);
                const uint32_t ad = s0 + GH_ARR + row * 80 + chunk * 16;
                LDSM_X4(b_hi[nt], ad);
                LDSM_X4(b_lo[nt], ad + GH_ARR);
            }
#pragma unroll
            for (int mt = 0; mt < 4; mt++)
#pragma unroll
                for (int j = 0; j < 4; j++)
                    MMA16816(acc[mt][j], a_f[mt],
                             b_hi[j >> 1][(j & 1) * 2], b_hi[j >> 1][(j & 1) * 2 + 1]);
#pragma unroll
            for (int mt = 0; mt < 4; mt++)
#pragma unroll
                for (int j = 0; j < 4; j++)
                    MMA16816(acc[mt][j], a_f[mt],
                             b_lo[j >> 1][(j & 1) * 2], b_lo[j >> 1][(j & 1) * 2 + 1]);
        }
    }

    const int gq = lane >> 2, tq = lane & 3;
#pragma unroll
    for (int mt = 0; mt < 4; mt++) {
#pragma unroll
        for (int j = 0; j < 4; j++) {
            const int col = bn + warp_n * 32 + j * 8 + tq * 2;
            float2 bb = make_float2(0.f, 0.f);
            if (EPI == 2 || EPI == 3) bb = *(const float2*)&bias[col];
#pragma unroll
            for (int rr = 0; rr < 2; rr++) {
                const int row = bm + warp_m * 64 + mt * 16 + gq + rr * 8;
                float vx = acc[mt][j][rr * 2 + 0];
                float vy = acc[mt][j][rr * 2 + 1];
                if (EPI == 2 || EPI == 3) { vx += bb.x; vy += bb.y; }
                if (EPI == 2) { vx = gelu_exact(vx); vy = gelu_exact(vy); }
                if (EPI == 1 || EPI == 3) {
                    const float2 rv = *(const float2*)&res[(size_t)row * N + col];
                    vx += rv.x; vy += rv.y;
                }
                if (OUTMODE == 2) {
                    *(__half2*)&Ch[(size_t)row * N + col] = __floats2half2_rn(vx, vy);
                } else {
                    *(float2*)&C[(size_t)row * N + col] = make_float2(vx, vy);
                }
            }
        }
    }
}

// ---------------------------------------------------------------------------
// HMMA flash attention. Grid (T/64, H, B), 128 threads = 4 warps.
// qkv fp16 [row][3072]: Q at hoff, K at 1024+hoff, V at 2048+hoff.
// Output: single fp16 at [row][hoff+d].
// ---------------------------------------------------------------------------
#define AQ_S 72                       // smem row stride in halfs (144 B)
#define ATT_Q     0
#define ATT_K(s)  (4608 + (s) * 4608)
#define ATT_V(s)  (13824 + (s) * 4608)
#define ATT_SMEM  (23040 * 2)         // 46080 B

__global__ __launch_bounds__(128, 3)
void attn_hmma(const __half* __restrict__ qkv, __half* __restrict__ ao) {
    extern __shared__ __half sh[];
    const uint32_t sb = smem_u32(sh);
    const int tid = threadIdx.x;
    const int lane = tid & 31, w = tid >> 5;
    const int b = blockIdx.z, h = blockIdx.y, qt = blockIdx.x;
    const int hoff = h * DHEAD;
    const int rowbase = b * TSEQ + qt * 64;

#pragma unroll
    for (int p = 0; p < 4; p++) {
        const int idx = tid + p * 128;
        const int r = idx >> 3, c8 = idx & 7;
        *(uint4*)(sh + ATT_Q + r * AQ_S + c8 * 8) =
            *(const uint4*)(qkv + (size_t)(rowbase + r) * 3072 + hoff + c8 * 8);
    }

    auto load_kv = [&](int st, int kt) {
        const int kvbase = b * TSEQ + kt * 64;
#pragma unroll
        for (int p = 0; p < 4; p++) {
            const int idx = tid + p * 128;
            const int r = idx >> 3, c8 = idx & 7;
            const __half* gk = qkv + (size_t)(kvbase + r) * 3072 + 1024 + hoff + c8 * 8;
            CP_ASYNC16(sb + 2 * (ATT_K(st) + r * AQ_S + c8 * 8), gk);
            CP_ASYNC16(sb + 2 * (ATT_V(st) + r * AQ_S + c8 * 8), gk + 1024);
        }
    };

    load_kv(0, 0); CP_COMMIT();
    __syncthreads();

    uint32_t qa[4][4];
    const int m0 = w * 16;
#pragma unroll
    for (int kk = 0; kk < 4; kk++) {
        const uint32_t ad = sb + 2 * (ATT_Q + (m0 + (lane & 15)) * AQ_S +
                                      kk * 16 + (lane >> 4) * 8);
        LDSM_X4(qa[kk], ad);
    }

    float m_[2] = {-1e30f, -1e30f}, l_[2] = {0.f, 0.f};
    float o[8][4];
#pragma unroll
    for (int n = 0; n < 8; n++)
#pragma unroll
        for (int j = 0; j < 4; j++) o[n][j] = 0.f;

    const int NT = TSEQ / 64;
    for (int kt = 0; kt < NT; kt++) {
        __syncthreads();
        if (kt + 1 < NT) load_kv((kt + 1) & 1, kt + 1);
        CP_COMMIT();
        CP_WAIT1();
        __syncthreads();
        const int s = kt & 1;

        float c[8][4];
#pragma unroll
        for (int n = 0; n < 8; n++)
#pragma unroll
            for (int j = 0; j < 4; j++) c[n][j] = 0.f;

#pragma unroll
        for (int kk2 = 0; kk2 < 2; kk2++) {
#pragma unroll
            for (int n = 0; n < 8; n++) {
                uint32_t bf[4];
                const uint32_t ad = sb + 2 * (ATT_K(s) + (n * 8 + (lane & 7)) * AQ_S +
                                              kk2 * 32 + (lane >> 3) * 8);
                LDSM_X4(bf, ad);
                MMA16816(c[n], qa[2 * kk2], bf[0], bf[1]);
                MMA16816(c[n], qa[2 * kk2 + 1], bf[2], bf[3]);
            }
        }

        float tm0 = -1e30f, tm1 = -1e30f;
#pragma unroll
        for (int n = 0; n < 8; n++) {
            tm0 = fmaxf(tm0, fmaxf(c[n][0], c[n][1]));
            tm1 = fmaxf(tm1, fmaxf(c[n][2], c[n][3]));
        }
#pragma unroll
        for (int ofs = 1; ofs <= 2; ofs <<= 1) {
            tm0 = fmaxf(tm0, __shfl_xor_sync(0xffffffffu, tm0, ofs));
            tm1 = fmaxf(tm1, __shfl_xor_sync(0xffffffffu, tm1, ofs));
        }
        tm0 *= 0.125f; tm1 *= 0.125f;
        const float mn0 = fmaxf(m_[0], tm0), mn1 = fmaxf(m_[1], tm1);
        const float al0 = __expf(m_[0] - mn0), al1 = __expf(m_[1] - mn1);
        m_[0] = mn0; m_[1] = mn1;

        uint32_t u01[8], u23[8];
        float rs0 = 0.f, rs1 = 0.f;
#pragma unroll
        for (int n = 0; n < 8; n++) {
            const float p0 = __expf(c[n][0] * 0.125f - mn0);
            const float p1 = __expf(c[n][1] * 0.125f - mn0);
            const float p2 = __expf(c[n][2] * 0.125f - mn1);
            const float p3 = __expf(c[n][3] * 0.125f - mn1);
            rs0 += p0 + p1; rs1 += p2 + p3;
            const __half2 h01 = __floats2half2_rn(p0, p1);
            const __half2 h23 = __floats2half2_rn(p2, p3);
            u01[n] = *(const uint32_t*)&h01;
            u23[n] = *(const uint32_t*)&h23;
        }
#pragma unroll
        for (int ofs = 1; ofs <= 2; ofs <<= 1) {
            rs0 += __shfl_xor_sync(0xffffffffu, rs0, ofs);
            rs1 += __shfl_xor_sync(0xffffffffu, rs1, ofs);
        }
        l_[0] = l_[0] * al0 + rs0;
        l_[1] = l_[1] * al1 + rs1;
#pragma unroll
        for (int n = 0; n < 8; n++) {
            o[n][0] *= al0; o[n][1] *= al0;
            o[n][2] *= al1; o[n][3] *= al1;
        }

#pragma unroll
        for (int kk = 0; kk < 4; kk++) {
            uint32_t au[4] = {u01[2 * kk], u23[2 * kk], u01[2 * kk + 1], u23[2 * kk + 1]};
#pragma unroll
            for (int n2 = 0; n2 < 4; n2++) {
                uint32_t bf[4];
                const uint32_t ad = sb + 2 * (ATT_V(s) + (kk * 16 + (lane & 15)) * AQ_S +
                                              n2 * 16 + (lane >> 4) * 8);
                LDSM_X4_T(bf, ad);
                MMA16816(o[2 * n2], au, bf[0], bf[1]);
                MMA16816(o[2 * n2 + 1], au, bf[2], bf[3]);
            }
        }
    }

    const float inv0 = 1.0f / l_[0], inv1 = 1.0f / l_[1];
    const int r0 = lane >> 2, tq = lane & 3;
    const int grow0 = rowbase + m0 + r0, grow1 = grow0 + 8;
#pragma unroll
    for (int n = 0; n < 8; n++) {
        const int col = hoff + n * 8 + tq * 2;
        *(__half2*)&ao[(size_t)grow0 * DMODEL + col] =
            __floats2half2_rn(o[n][0] * inv0, o[n][1] * inv0);
        *(__half2*)&ao[(size_t)grow1 * DMODEL + col] =
            __floats2half2_rn(o[n][2] * inv1, o[n][3] * inv1);
    }
}

// ---------------------------------------------------------------------------
// Launcher
// ---------------------------------------------------------------------------
extern "C" void kernel_launch(void* const* d_in, const int* in_sizes, int n_in,
                              void* d_out, int out_size) {
    const float* x     = (const float*)d_in[0];
    const float* ln1_s = (const float*)d_in[1];
    const float* ln1_b = (const float*)d_in[2];
    const float* qkv_w = (const float*)d_in[3];
    const float* out_w = (const float*)d_in[4];
    const float* ln2_s = (const float*)d_in[5];
    const float* ln2_b = (const float*)d_in[6];
    const float* fc1_w = (const float*)d_in[7];
    const float* fc1_b = (const float*)d_in[8];
    const float* fc2_w = (const float*)d_in[9];
    const float* fc2_b = (const float*)d_in[10];
    float* out = (float*)d_out;

    float *x1_p;
    __half *qkvh, *act, *ff;
    __half *wqh, *wql, *woh, *wol, *w1h, *w1l, *w2h, *w2l;
    cudaGetSymbolAddress((void**)&x1_p, g_x1);
    cudaGetSymbolAddress((void**)&qkvh, g_qkvh);
    cudaGetSymbolAddress((void**)&act, g_act);
    cudaGetSymbolAddress((void**)&ff, g_ff);
    cudaGetSymbolAddress((void**)&wqh, g_wqkv_hi);
    cudaGetSymbolAddress((void**)&wql, g_wqkv_lo);
    cudaGetSymbolAddress((void**)&woh, g_wout_hi);
    cudaGetSymbolAddress((void**)&wol, g_wout_lo);
    cudaGetSymbolAddress((void**)&w1h, g_wfc1_hi);
    cudaGetSymbolAddress((void**)&w1l, g_wfc1_lo);
    cudaGetSymbolAddress((void**)&w2h, g_wfc2_hi);
    cudaGetSymbolAddress((void**)&w2l, g_wfc2_lo);

    cudaFuncSetAttribute(gemm_hmma<0, 2>, cudaFuncAttributeMaxDynamicSharedMemorySize, GH_SMEM);
    cudaFuncSetAttribute(gemm_hmma<1, 0>, cudaFuncAttributeMaxDynamicSharedMemorySize, GH_SMEM);
    cudaFuncSetAttribute(gemm_hmma<2, 2>, cudaFuncAttributeMaxDynamicSharedMemorySize, GH_SMEM);
    cudaFuncSetAttribute(gemm_hmma<3, 0>, cudaFuncAttributeMaxDynamicSharedMemorySize, GH_SMEM);

    // 0) Weight splits (fp32 -> hi/lo fp16)
    split_kernel<<<3 * DMODEL * DMODEL / 4 / 256, 256>>>(qkv_w, wqh, wql, 3 * DMODEL * DMODEL / 4);
    split_kernel<<<DMODEL * DMODEL / 4 / 256, 256>>>(out_w, woh, wol, DMODEL * DMODEL / 4);
    split_kernel<<<DFF * DMODEL / 4 / 256, 256>>>(fc1_w, w1h, w1l, DFF * DMODEL / 4);
    split_kernel<<<DMODEL * DFF / 4 / 256, 256>>>(fc2_w, w2h, w2l, DMODEL * DFF / 4);

    // 1) LN1 -> fp16 activations
    ln_kernel<<<MROWS, 256>>>(x, ln1_s, ln1_b, act);

    // 2) QKV projection -> fp16
    gemm_hmma<0, 2><<<dim3(3 * DMODEL / 128, MROWS / 128), 256, GH_SMEM>>>(
        act, wqh, wql, nullptr, qkvh, MROWS, 3 * DMODEL, DMODEL, nullptr, nullptr);

    // 3) HMMA flash attention -> fp16
    attn_hmma<<<dim3(TSEQ / 64, NHEAD, BATCH), 128, ATT_SMEM>>>(qkvh, act);

    // 4) Out projection + residual -> x1 fp32
    gemm_hmma<1, 0><<<dim3(DMODEL / 128, MROWS / 128), 256, GH_SMEM>>>(
        act, woh, wol, x1_p, nullptr, MROWS, DMODEL, DMODEL, nullptr, x);

    // 5) LN2 -> fp16 activations
    ln_kernel<<<MROWS, 256>>>(x1_p, ln2_s, ln2_b, act);

    // 6) FC1 + bias + GELU -> fp16
    gemm_hmma<2, 2><<<dim3(DFF / 128, MROWS / 128), 256, GH_SMEM>>>(
        act, w1h, w1l, nullptr, ff, MROWS, DFF, DMODEL, fc1_b, nullptr);

    // 7) FC2 + bias + residual -> out fp32
    gemm_hmma<3, 0><<<dim3(DMODEL / 128, MROWS / 128), 256, GH_SMEM>>>(
        ff, w2h, w2l, out, nullptr, MROWS, DMODEL, DFF, fc2_b, x1_p);
}

// round 6
// speedup vs baseline: 4.8220x; 1.2637x over previous
#include <cuda_runtime.h>
#include <cuda_fp16.h>
#include <math.h>
#include <stdint.h>

// Problem constants
#define BATCH 4
#define TSEQ 2048
#define DMODEL 1024
#define NHEAD 16
#define DHEAD 64
#define DFF 4096
#define MROWS (BATCH * TSEQ)   // 8192

// ---------------------------------------------------------------------------
// Scratch (device globals; no runtime allocation allowed)
// ---------------------------------------------------------------------------
__device__ float  g_x1[(size_t)MROWS * DMODEL];        // 32 MB fp32
__device__ __half g_qkvh[(size_t)MROWS * 3 * DMODEL];  // 48 MB fp16
__device__ __half g_act[(size_t)MROWS * DMODEL];       // activations fp16
__device__ __half g_ff[(size_t)MROWS * DFF];           // GELU out fp16
__device__ __half g_wqkv_hi[(size_t)3 * DMODEL * DMODEL];
__device__ __half g_wout_hi[(size_t)DMODEL * DMODEL];
__device__ __half g_wfc1_hi[(size_t)DFF * DMODEL];
__device__ __half g_wfc1_lo[(size_t)DFF * DMODEL];
__device__ __half g_wfc2_hi[(size_t)DMODEL * DFF];
__device__ __half g_wfc2_lo[(size_t)DMODEL * DFF];

// ---------------------------------------------------------------------------
// Helpers
// ---------------------------------------------------------------------------
__device__ __forceinline__ uint32_t smem_u32(const void* p) {
    uint32_t a;
    asm("{ .reg .u64 t; cvta.to.shared.u64 t, %1; cvt.u32.u64 %0, t; }"
        : "=r"(a) : "l"(p));
    return a;
}

#define LDSM_X4(d, a)                                                        \
    asm volatile("ldmatrix.sync.aligned.m8n8.x4.shared.b16 "                 \
                 "{%0,%1,%2,%3}, [%4];"                                      \
                 : "=r"((d)[0]), "=r"((d)[1]), "=r"((d)[2]), "=r"((d)[3])    \
                 : "r"(a))

#define LDSM_X4_T(d, a)                                                      \
    asm volatile("ldmatrix.sync.aligned.m8n8.x4.trans.shared.b16 "           \
                 "{%0,%1,%2,%3}, [%4];"                                      \
                 : "=r"((d)[0]), "=r"((d)[1]), "=r"((d)[2]), "=r"((d)[3])    \
                 : "r"(a))

#define MMA16816(c, a, b0, b1)                                               \
    asm volatile("mma.sync.aligned.m16n8k16.row.col.f32.f16.f16.f32 "        \
                 "{%0,%1,%2,%3},{%4,%5,%6,%7},{%8,%9},{%0,%1,%2,%3};"        \
                 : "+f"((c)[0]), "+f"((c)[1]), "+f"((c)[2]), "+f"((c)[3])    \
                 : "r"((a)[0]), "r"((a)[1]), "r"((a)[2]), "r"((a)[3]),       \
                   "r"(b0), "r"(b1))

#define CP_ASYNC16(s, g) \
    asm volatile("cp.async.cg.shared.global [%0], [%1], 16;" :: "r"(s), "l"(g))
#define CP_COMMIT() asm volatile("cp.async.commit_group;")
#define CP_WAIT1()  asm volatile("cp.async.wait_group 1;")

__device__ __forceinline__ float gelu_exact(float x) {
    return 0.5f * x * (1.0f + erff(x * 0.70710678118654752f));
}

__device__ __forceinline__ void split16(float v, __half& hi, __half& lo) {
    hi = __float2half_rn(v);
    lo = __float2half_rn(v - __half2float(hi));
}

// ---------------------------------------------------------------------------
// Weight prep: fp32 -> (hi, lo) fp16 split, or plain fp16 convert
// ---------------------------------------------------------------------------
__global__ __launch_bounds__(256)
void split_kernel(const float* __restrict__ in, __half* __restrict__ hi,
                  __half* __restrict__ lo, int n4) {
    const int i = blockIdx.x * 256 + threadIdx.x;
    if (i >= n4) return;
    const float4 v = ((const float4*)in)[i];
    __half hx, lx, hy, ly, hz, lz, hw, lw;
    split16(v.x, hx, lx); split16(v.y, hy, ly);
    split16(v.z, hz, lz); split16(v.w, hw, lw);
    ((__half2*)hi)[i * 2 + 0] = __halves2half2(hx, hy);
    ((__half2*)hi)[i * 2 + 1] = __halves2half2(hz, hw);
    ((__half2*)lo)[i * 2 + 0] = __halves2half2(lx, ly);
    ((__half2*)lo)[i * 2 + 1] = __halves2half2(lz, lw);
}

__global__ __launch_bounds__(256)
void cvt_kernel(const float* __restrict__ in, __half* __restrict__ hi, int n4) {
    const int i = blockIdx.x * 256 + threadIdx.x;
    if (i >= n4) return;
    const float4 v = ((const float4*)in)[i];
    ((__half2*)hi)[i * 2 + 0] = __floats2half2_rn(v.x, v.y);
    ((__half2*)hi)[i * 2 + 1] = __floats2half2_rn(v.z, v.w);
}

// ---------------------------------------------------------------------------
// LayerNorm -> single fp16
// ---------------------------------------------------------------------------
__global__ __launch_bounds__(256)
void ln_kernel(const float* __restrict__ x, const float* __restrict__ sc,
               const float* __restrict__ bi, __half* __restrict__ y) {
    const int row = blockIdx.x;
    const int t = threadIdx.x;
    const float4 v = *(const float4*)(x + (size_t)row * DMODEL + t * 4);
    float s = v.x + v.y + v.z + v.w;
    float s2 = v.x * v.x + v.y * v.y + v.z * v.z + v.w * v.w;
#pragma unroll
    for (int o = 16; o; o >>= 1) {
        s  += __shfl_xor_sync(0xffffffffu, s, o);
        s2 += __shfl_xor_sync(0xffffffffu, s2, o);
    }
    __shared__ float rs[8], rs2[8];
    if ((t & 31) == 0) { rs[t >> 5] = s; rs2[t >> 5] = s2; }
    __syncthreads();
    s = 0.f; s2 = 0.f;
#pragma unroll
    for (int i = 0; i < 8; i++) { s += rs[i]; s2 += rs2[i]; }
    const float mu = s * (1.0f / DMODEL);
    const float var = s2 * (1.0f / DMODEL) - mu * mu;
    const float r = rsqrtf(var + 1e-5f);
    const float4 g4 = *(const float4*)(sc + t * 4);
    const float4 b4 = *(const float4*)(bi + t * 4);
    float4 o4;
    o4.x = (v.x - mu) * r * g4.x + b4.x;
    o4.y = (v.y - mu) * r * g4.y + b4.y;
    o4.z = (v.z - mu) * r * g4.z + b4.z;
    o4.w = (v.w - mu) * r * g4.w + b4.w;
    const size_t off = (size_t)row * DMODEL + t * 4;
    ((__half2*)(y + off))[0] = __floats2half2_rn(o4.x, o4.y);
    ((__half2*)(y + off))[1] = __floats2half2_rn(o4.z, o4.w);
}

// ---------------------------------------------------------------------------
// HMMA GEMM: C[M,N] = A[M,K] @ W[N,K]^T
//   NTERMS=1: W single fp16 (Bh)        -> acc += A*Wh
//   NTERMS=2: W split hi/lo fp16 (exact)-> acc += A*Wh + A*Wl
//   EPI 0: none | 1: +res | 2: +bias,GELU | 3: +bias+res
//   OUTMODE 0: fp32 C | 2: single fp16 Ch
// CTA tile 128x128, BK=32, 8 warps (64x32), 2-stage cp.async, 2 CTAs/SM.
// ---------------------------------------------------------------------------
#define GH_ARR 10240

template <int EPI, int OUTMODE, int NTERMS>
__global__ __launch_bounds__(256, 2)
void gemm_hmma(const __half* __restrict__ Ah, const __half* __restrict__ Bh,
               const __half* __restrict__ Bl,
               float* __restrict__ C, __half* __restrict__ Ch,
               int M, int N, int K,
               const float* __restrict__ bias, const float* __restrict__ res) {
    constexpr int NARR = 1 + NTERMS;
    constexpr int STAGE = NARR * GH_ARR;
    extern __shared__ char sm[];
    const uint32_t sb = smem_u32(sm);
    const int tid = threadIdx.x;
    const int lane = tid & 31, wid = tid >> 5;
    const int warp_m = wid >> 2, warp_n = wid & 3;
    const int bm = blockIdx.y * 128, bn = blockIdx.x * 128;
    const int NT = K >> 5;

    auto load_stage = [&](int st, int kt) {
        const int k0 = kt * 32;
        const uint32_t so = sb + st * STAGE;
#pragma unroll
        for (int arr = 0; arr < NARR; arr++) {
            const __half* src = (arr == 0) ? Ah : (arr == 1) ? Bh : Bl;
            const int base = (arr == 0) ? bm : bn;
#pragma unroll
            for (int i = 0; i < 2; i++) {
                const int idx = tid + i * 256;
                const int r = idx >> 2, kc = idx & 3;
                const void* g = src + (size_t)(base + r) * K + k0 + kc * 8;
                CP_ASYNC16(so + arr * GH_ARR + r * 80 + kc * 16, g);
            }
        }
    };

    load_stage(0, 0); CP_COMMIT();

    float acc[4][4][4];
#pragma unroll
    for (int a = 0; a < 4; a++)
#pragma unroll
        for (int b = 0; b < 4; b++)
#pragma unroll
            for (int c = 0; c < 4; c++) acc[a][b][c] = 0.f;

    for (int kt = 0; kt < NT; kt++) {
        if (kt + 1 < NT) load_stage((kt + 1) & 1, kt + 1);
        CP_COMMIT();
        CP_WAIT1();
        __syncthreads();

        const uint32_t s0 = sb + (kt & 1) * STAGE;
#pragma unroll
        for (int kh = 0; kh < 2; kh++) {
            uint32_t a_f[4][4], b_hi[2][4], b_lo[2][4];
#pragma unroll
            for (int mt = 0; mt < 4; mt++) {
                const int row = warp_m * 64 + mt * 16 + (lane & 15);
                const int chunk = kh * 2 + (lane >> 4);
                LDSM_X4(a_f[mt], s0 + row * 80 + chunk * 16);
            }
#pragma unroll
            for (int nt = 0; nt < 2; nt++) {
                const int row = warp_n * 32 + nt * 16 + (lane & 7) + ((lane >> 4) << 3);
                const int chunk = kh * 2 + ((lane >> 3) & 1);
                const uint32_t ad = s0 + GH_ARR + row * 80 + chunk * 16;
                LDSM_X4(b_hi[nt], ad);
                if (NTERMS == 2) LDSM_X4(b_lo[nt], ad + GH_ARR);
            }
#pragma unroll
            for (int mt = 0; mt < 4; mt++)
#pragma unroll
                for (int j = 0; j < 4; j++)
                    MMA16816(acc[mt][j], a_f[mt],
                             b_hi[j >> 1][(j & 1) * 2], b_hi[j >> 1][(j & 1) * 2 + 1]);
            if (NTERMS == 2) {
#pragma unroll
                for (int mt = 0; mt < 4; mt++)
#pragma unroll
                    for (int j = 0; j < 4; j++)
                        MMA16816(acc[mt][j], a_f[mt],
                                 b_lo[j >> 1][(j & 1) * 2], b_lo[j >> 1][(j & 1) * 2 + 1]);
            }
        }
        __syncthreads();
    }

    const int gq = lane >> 2, tq = lane & 3;
#pragma unroll
    for (int mt = 0; mt < 4; mt++) {
#pragma unroll
        for (int j = 0; j < 4; j++) {
            const int col = bn + warp_n * 32 + j * 8 + tq * 2;
            float2 bb = make_float2(0.f, 0.f);
            if (EPI == 2 || EPI == 3) bb = *(const float2*)&bias[col];
#pragma unroll
            for (int rr = 0; rr < 2; rr++) {
                const int row = bm + warp_m * 64 + mt * 16 + gq + rr * 8;
                float vx = acc[mt][j][rr * 2 + 0];
                float vy = acc[mt][j][rr * 2 + 1];
                if (EPI == 2 || EPI == 3) { vx += bb.x; vy += bb.y; }
                if (EPI == 2) { vx = gelu_exact(vx); vy = gelu_exact(vy); }
                if (EPI == 1 || EPI == 3) {
                    const float2 rv = *(const float2*)&res[(size_t)row * N + col];
                    vx += rv.x; vy += rv.y;
                }
                if (OUTMODE == 2) {
                    *(__half2*)&Ch[(size_t)row * N + col] = __floats2half2_rn(vx, vy);
                } else {
                    *(float2*)&C[(size_t)row * N + col] = make_float2(vx, vy);
                }
            }
        }
    }
}

// ---------------------------------------------------------------------------
// HMMA flash attention. Grid (T/64, H, B), 128 threads = 4 warps.
// ---------------------------------------------------------------------------
#define AQ_S 72
#define ATT_Q     0
#define ATT_K(s)  (4608 + (s) * 4608)
#define ATT_V(s)  (13824 + (s) * 4608)
#define ATT_SMEM  (23040 * 2)

__global__ __launch_bounds__(128, 3)
void attn_hmma(const __half* __restrict__ qkv, __half* __restrict__ ao) {
    extern __shared__ __half sh[];
    const uint32_t sb = smem_u32(sh);
    const int tid = threadIdx.x;
    const int lane = tid & 31, w = tid >> 5;
    const int b = blockIdx.z, h = blockIdx.y, qt = blockIdx.x;
    const int hoff = h * DHEAD;
    const int rowbase = b * TSEQ + qt * 64;

#pragma unroll
    for (int p = 0; p < 4; p++) {
        const int idx = tid + p * 128;
        const int r = idx >> 3, c8 = idx & 7;
        *(uint4*)(sh + ATT_Q + r * AQ_S + c8 * 8) =
            *(const uint4*)(qkv + (size_t)(rowbase + r) * 3072 + hoff + c8 * 8);
    }

    auto load_kv = [&](int st, int kt) {
        const int kvbase = b * TSEQ + kt * 64;
#pragma unroll
        for (int p = 0; p < 4; p++) {
            const int idx = tid + p * 128;
            const int r = idx >> 3, c8 = idx & 7;
            const __half* gk = qkv + (size_t)(kvbase + r) * 3072 + 1024 + hoff + c8 * 8;
            CP_ASYNC16(sb + 2 * (ATT_K(st) + r * AQ_S + c8 * 8), gk);
            CP_ASYNC16(sb + 2 * (ATT_V(st) + r * AQ_S + c8 * 8), gk + 1024);
        }
    };

    load_kv(0, 0); CP_COMMIT();
    __syncthreads();

    uint32_t qa[4][4];
    const int m0 = w * 16;
#pragma unroll
    for (int kk = 0; kk < 4; kk++) {
        const uint32_t ad = sb + 2 * (ATT_Q + (m0 + (lane & 15)) * AQ_S +
                                      kk * 16 + (lane >> 4) * 8);
        LDSM_X4(qa[kk], ad);
    }

    float m_[2] = {-1e30f, -1e30f}, l_[2] = {0.f, 0.f};
    float o[8][4];
#pragma unroll
    for (int n = 0; n < 8; n++)
#pragma unroll
        for (int j = 0; j < 4; j++) o[n][j] = 0.f;

    const int NT = TSEQ / 64;
    for (int kt = 0; kt < NT; kt++) {
        __syncthreads();
        if (kt + 1 < NT) load_kv((kt + 1) & 1, kt + 1);
        CP_COMMIT();
        CP_WAIT1();
        __syncthreads();
        const int s = kt & 1;

        float c[8][4];
#pragma unroll
        for (int n = 0; n < 8; n++)
#pragma unroll
            for (int j = 0; j < 4; j++) c[n][j] = 0.f;

#pragma unroll
        for (int kk2 = 0; kk2 < 2; kk2++) {
#pragma unroll
            for (int n = 0; n < 8; n++) {
                uint32_t bf[4];
                const uint32_t ad = sb + 2 * (ATT_K(s) + (n * 8 + (lane & 7)) * AQ_S +
                                              kk2 * 32 + (lane >> 3) * 8);
                LDSM_X4(bf, ad);
                MMA16816(c[n], qa[2 * kk2], bf[0], bf[1]);
                MMA16816(c[n], qa[2 * kk2 + 1], bf[2], bf[3]);
            }
        }

        float tm0 = -1e30f, tm1 = -1e30f;
#pragma unroll
        for (int n = 0; n < 8; n++) {
            tm0 = fmaxf(tm0, fmaxf(c[n][0], c[n][1]));
            tm1 = fmaxf(tm1, fmaxf(c[n][2], c[n][3]));
        }
#pragma unroll
        for (int ofs = 1; ofs <= 2; ofs <<= 1) {
            tm0 = fmaxf(tm0, __shfl_xor_sync(0xffffffffu, tm0, ofs));
            tm1 = fmaxf(tm1, __shfl_xor_sync(0xffffffffu, tm1, ofs));
        }
        tm0 *= 0.125f; tm1 *= 0.125f;
        const float mn0 = fmaxf(m_[0], tm0), mn1 = fmaxf(m_[1], tm1);
        const float al0 = __expf(m_[0] - mn0), al1 = __expf(m_[1] - mn1);
        m_[0] = mn0; m_[1] = mn1;

        uint32_t u01[8], u23[8];
        float rs0 = 0.f, rs1 = 0.f;
#pragma unroll
        for (int n = 0; n < 8; n++) {
            const float p0 = __expf(c[n][0] * 0.125f - mn0);
            const float p1 = __expf(c[n][1] * 0.125f - mn0);
            const float p2 = __expf(c[n][2] * 0.125f - mn1);
            const float p3 = __expf(c[n][3] * 0.125f - mn1);
            rs0 += p0 + p1; rs1 += p2 + p3;
            const __half2 h01 = __floats2half2_rn(p0, p1);
            const __half2 h23 = __floats2half2_rn(p2, p3);
            u01[n] = *(const uint32_t*)&h01;
            u23[n] = *(const uint32_t*)&h23;
        }
#pragma unroll
        for (int ofs = 1; ofs <= 2; ofs <<= 1) {
            rs0 += __shfl_xor_sync(0xffffffffu, rs0, ofs);
            rs1 += __shfl_xor_sync(0xffffffffu, rs1, ofs);
        }
        l_[0] = l_[0] * al0 + rs0;
        l_[1] = l_[1] * al1 + rs1;
#pragma unroll
        for (int n = 0; n < 8; n++) {
            o[n][0] *= al0; o[n][1] *= al0;
            o[n][2] *= al1; o[n][3] *= al1;
        }

#pragma unroll
        for (int kk = 0; kk < 4; kk++) {
            uint32_t au[4] = {u01[2 * kk], u23[2 * kk], u01[2 * kk + 1], u23[2 * kk + 1]};
#pragma unroll
            for (int n2 = 0; n2 < 4; n2++) {
                uint32_t bf[4];
                const uint32_t ad = sb + 2 * (ATT_V(s) + (kk * 16 + (lane & 15)) * AQ_S +
                                              n2 * 16 + (lane >> 4) * 8);
                LDSM_X4_T(bf, ad);
                MMA16816(o[2 * n2], au, bf[0], bf[1]);
                MMA16816(o[2 * n2 + 1], au, bf[2], bf[3]);
            }
        }
    }

    const float inv0 = 1.0f / l_[0], inv1 = 1.0f / l_[1];
    const int r0 = lane >> 2, tq = lane & 3;
    const int grow0 = rowbase + m0 + r0, grow1 = grow0 + 8;
#pragma unroll
    for (int n = 0; n < 8; n++) {
        const int col = hoff + n * 8 + tq * 2;
        *(__half2*)&ao[(size_t)grow0 * DMODEL + col] =
            __floats2half2_rn(o[n][0] * inv0, o[n][1] * inv0);
        *(__half2*)&ao[(size_t)grow1 * DMODEL + col] =
            __floats2half2_rn(o[n][2] * inv1, o[n][3] * inv1);
    }
}

// ---------------------------------------------------------------------------
// Launcher
// ---------------------------------------------------------------------------
extern "C" void kernel_launch(void* const* d_in, const int* in_sizes, int n_in,
                              void* d_out, int out_size) {
    const float* x     = (const float*)d_in[0];
    const float* ln1_s = (const float*)d_in[1];
    const float* ln1_b = (const float*)d_in[2];
    const float* qkv_w = (const float*)d_in[3];
    const float* out_w = (const float*)d_in[4];
    const float* ln2_s = (const float*)d_in[5];
    const float* ln2_b = (const float*)d_in[6];
    const float* fc1_w = (const float*)d_in[7];
    const float* fc1_b = (const float*)d_in[8];
    const float* fc2_w = (const float*)d_in[9];
    const float* fc2_b = (const float*)d_in[10];
    float* out = (float*)d_out;

    float *x1_p;
    __half *qkvh, *act, *ff;
    __half *wqh, *woh, *w1h, *w1l, *w2h, *w2l;
    cudaGetSymbolAddress((void**)&x1_p, g_x1);
    cudaGetSymbolAddress((void**)&qkvh, g_qkvh);
    cudaGetSymbolAddress((void**)&act, g_act);
    cudaGetSymbolAddress((void**)&ff, g_ff);
    cudaGetSymbolAddress((void**)&wqh, g_wqkv_hi);
    cudaGetSymbolAddress((void**)&woh, g_wout_hi);
    cudaGetSymbolAddress((void**)&w1h, g_wfc1_hi);
    cudaGetSymbolAddress((void**)&w1l, g_wfc1_lo);
    cudaGetSymbolAddress((void**)&w2h, g_wfc2_hi);
    cudaGetSymbolAddress((void**)&w2l, g_wfc2_lo);

    const int SMEM1 = 2 * 2 * GH_ARR;   // 1-term, 2 stages
    const int SMEM2 = 2 * 3 * GH_ARR;   // 2-term, 2 stages
    cudaFuncSetAttribute(gemm_hmma<0, 2, 1>, cudaFuncAttributeMaxDynamicSharedMemorySize, SMEM1);
    cudaFuncSetAttribute(gemm_hmma<1, 0, 1>, cudaFuncAttributeMaxDynamicSharedMemorySize, SMEM1);
    cudaFuncSetAttribute(gemm_hmma<2, 2, 2>, cudaFuncAttributeMaxDynamicSharedMemorySize, SMEM2);
    cudaFuncSetAttribute(gemm_hmma<3, 0, 2>, cudaFuncAttributeMaxDynamicSharedMemorySize, SMEM2);

    // 0) Weight prep: fp16 convert for qkv/out, hi/lo split for fc1/fc2
    cvt_kernel<<<3 * DMODEL * DMODEL / 4 / 256, 256>>>(qkv_w, wqh, 3 * DMODEL * DMODEL / 4);
    cvt_kernel<<<DMODEL * DMODEL / 4 / 256, 256>>>(out_w, woh, DMODEL * DMODEL / 4);
    split_kernel<<<DFF * DMODEL / 4 / 256, 256>>>(fc1_w, w1h, w1l, DFF * DMODEL / 4);
    split_kernel<<<DMODEL * DFF / 4 / 256, 256>>>(fc2_w, w2h, w2l, DMODEL * DFF / 4);

    // 1) LN1 -> fp16 activations
    ln_kernel<<<MROWS, 256>>>(x, ln1_s, ln1_b, act);

    // 2) QKV projection (1-term fp16 weights) -> fp16
    gemm_hmma<0, 2, 1><<<dim3(3 * DMODEL / 128, MROWS / 128), 256, SMEM1>>>(
        act, wqh, nullptr, nullptr, qkvh, MROWS, 3 * DMODEL, DMODEL, nullptr, nullptr);

    // 3) HMMA flash attention -> fp16
    attn_hmma<<<dim3(TSEQ / 64, NHEAD, BATCH), 128, ATT_SMEM>>>(qkvh, act);

    // 4) Out projection (1-term) + residual -> x1 fp32
    gemm_hmma<1, 0, 1><<<dim3(DMODEL / 128, MROWS / 128), 256, SMEM1>>>(
        act, woh, nullptr, x1_p, nullptr, MROWS, DMODEL, DMODEL, nullptr, x);

    // 5) LN2 -> fp16 activations
    ln_kernel<<<MROWS, 256>>>(x1_p, ln2_s, ln2_b, act);

    // 6) FC1 (2-term) + bias + GELU -> fp16
    gemm_hmma<2, 2, 2><<<dim3(DFF / 128, MROWS / 128), 256, SMEM2>>>(
        act, w1h, w1l, nullptr, ff, MROWS, DFF, DMODEL, fc1_b, nullptr);

    // 7) FC2 (2-term) + bias + residual -> out fp32
    gemm_hmma<3, 0, 2><<<dim3(DMODEL / 128, MROWS / 128), 256, SMEM2>>>(
        ff, w2h, w2l, out, nullptr, MROWS, DMODEL, DFF, fc2_b, x1_p);
}

// round 7
// speedup vs baseline: 6.4510x; 1.3378x over previous
#include <cuda_runtime.h>
#include <cuda_fp16.h>
#include <math.h>
#include <stdint.h>

// Problem constants
#define BATCH 4
#define TSEQ 2048
#define DMODEL 1024
#define NHEAD 16
#define DHEAD 64
#define DFF 4096
#define MROWS (BATCH * TSEQ)   // 8192

// ---------------------------------------------------------------------------
// Scratch (device globals; no runtime allocation allowed)
// ---------------------------------------------------------------------------
__device__ float  g_x1[(size_t)MROWS * DMODEL];        // 32 MB fp32
__device__ __half g_qkvh[(size_t)MROWS * 3 * DMODEL];  // 48 MB fp16
__device__ __half g_act[(size_t)MROWS * DMODEL];       // activations fp16
__device__ __half g_ff[(size_t)MROWS * DFF];           // GELU out fp16
__device__ __half g_wqkv[(size_t)3 * DMODEL * DMODEL];
__device__ __half g_wout[(size_t)DMODEL * DMODEL];
__device__ __half g_wfc1[(size_t)DFF * DMODEL];
__device__ __half g_wfc2[(size_t)DMODEL * DFF];

// ---------------------------------------------------------------------------
// Helpers
// ---------------------------------------------------------------------------
__device__ __forceinline__ uint32_t smem_u32(const void* p) {
    uint32_t a;
    asm("{ .reg .u64 t; cvta.to.shared.u64 t, %1; cvt.u32.u64 %0, t; }"
        : "=r"(a) : "l"(p));
    return a;
}

#define LDSM_X4(d, a)                                                        \
    asm volatile("ldmatrix.sync.aligned.m8n8.x4.shared.b16 "                 \
                 "{%0,%1,%2,%3}, [%4];"                                      \
                 : "=r"((d)[0]), "=r"((d)[1]), "=r"((d)[2]), "=r"((d)[3])    \
                 : "r"(a))

#define LDSM_X4_T(d, a)                                                      \
    asm volatile("ldmatrix.sync.aligned.m8n8.x4.trans.shared.b16 "           \
                 "{%0,%1,%2,%3}, [%4];"                                      \
                 : "=r"((d)[0]), "=r"((d)[1]), "=r"((d)[2]), "=r"((d)[3])    \
                 : "r"(a))

#define MMA16816(c, a, b0, b1)                                               \
    asm volatile("mma.sync.aligned.m16n8k16.row.col.f32.f16.f16.f32 "        \
                 "{%0,%1,%2,%3},{%4,%5,%6,%7},{%8,%9},{%0,%1,%2,%3};"        \
                 : "+f"((c)[0]), "+f"((c)[1]), "+f"((c)[2]), "+f"((c)[3])    \
                 : "r"((a)[0]), "r"((a)[1]), "r"((a)[2]), "r"((a)[3]),       \
                   "r"(b0), "r"(b1))

#define CP_ASYNC16(s, g) \
    asm volatile("cp.async.cg.shared.global [%0], [%1], 16;" :: "r"(s), "l"(g))
#define CP_COMMIT() asm volatile("cp.async.commit_group;")
#define CP_WAIT1()  asm volatile("cp.async.wait_group 1;")

__device__ __forceinline__ float gelu_exact(float x) {
    return 0.5f * x * (1.0f + erff(x * 0.70710678118654752f));
}

// ---------------------------------------------------------------------------
// Weight convert: fp32 -> fp16
// ---------------------------------------------------------------------------
__global__ __launch_bounds__(256)
void cvt_kernel(const float* __restrict__ in, __half* __restrict__ hi, int n4) {
    const int i = blockIdx.x * 256 + threadIdx.x;
    if (i >= n4) return;
    const float4 v = ((const float4*)in)[i];
    ((__half2*)hi)[i * 2 + 0] = __floats2half2_rn(v.x, v.y);
    ((__half2*)hi)[i * 2 + 1] = __floats2half2_rn(v.z, v.w);
}

// ---------------------------------------------------------------------------
// LayerNorm -> single fp16
// ---------------------------------------------------------------------------
__global__ __launch_bounds__(256)
void ln_kernel(const float* __restrict__ x, const float* __restrict__ sc,
               const float* __restrict__ bi, __half* __restrict__ y) {
    const int row = blockIdx.x;
    const int t = threadIdx.x;
    const float4 v = *(const float4*)(x + (size_t)row * DMODEL + t * 4);
    float s = v.x + v.y + v.z + v.w;
    float s2 = v.x * v.x + v.y * v.y + v.z * v.z + v.w * v.w;
#pragma unroll
    for (int o = 16; o; o >>= 1) {
        s  += __shfl_xor_sync(0xffffffffu, s, o);
        s2 += __shfl_xor_sync(0xffffffffu, s2, o);
    }
    __shared__ float rs[8], rs2[8];
    if ((t & 31) == 0) { rs[t >> 5] = s; rs2[t >> 5] = s2; }
    __syncthreads();
    s = 0.f; s2 = 0.f;
#pragma unroll
    for (int i = 0; i < 8; i++) { s += rs[i]; s2 += rs2[i]; }
    const float mu = s * (1.0f / DMODEL);
    const float var = s2 * (1.0f / DMODEL) - mu * mu;
    const float r = rsqrtf(var + 1e-5f);
    const float4 g4 = *(const float4*)(sc + t * 4);
    const float4 b4 = *(const float4*)(bi + t * 4);
    float4 o4;
    o4.x = (v.x - mu) * r * g4.x + b4.x;
    o4.y = (v.y - mu) * r * g4.y + b4.y;
    o4.z = (v.z - mu) * r * g4.z + b4.z;
    o4.w = (v.w - mu) * r * g4.w + b4.w;
    const size_t off = (size_t)row * DMODEL + t * 4;
    ((__half2*)(y + off))[0] = __floats2half2_rn(o4.x, o4.y);
    ((__half2*)(y + off))[1] = __floats2half2_rn(o4.z, o4.w);
}

// ---------------------------------------------------------------------------
// HMMA fp16 GEMM: C[M,N] = A[M,K] @ W[N,K]^T, fp32 accumulate.
//   EPI 0: none | 1: +res | 2: +bias,GELU | 3: +bias+res
//   OUTMODE 0: fp32 C | 2: single fp16 Ch
// CTA tile 128x128, BK=32, 8 warps (64x32), 3-stage cp.async, 2 CTAs/SM.
// smem: 3 stages x 2 arrays (A, B) x 128 rows x 80B = 61440 B
// ---------------------------------------------------------------------------
#define GH_ARR   10240
#define GH_STAGE (2 * GH_ARR)
#define GH_SMEM  (3 * GH_STAGE)

template <int EPI, int OUTMODE>
__global__ __launch_bounds__(256, 2)
void gemm_hmma(const __half* __restrict__ Ah, const __half* __restrict__ Bh,
               float* __restrict__ C, __half* __restrict__ Ch,
               int M, int N, int K,
               const float* __restrict__ bias, const float* __restrict__ res) {
    extern __shared__ char sm[];
    const uint32_t sb = smem_u32(sm);
    const int tid = threadIdx.x;
    const int lane = tid & 31, wid = tid >> 5;
    const int warp_m = wid >> 2, warp_n = wid & 3;
    const int bm = blockIdx.y * 128, bn = blockIdx.x * 128;
    const int NT = K >> 5;

    auto load_stage = [&](int st, int kt) {
        const int k0 = kt * 32;
        const uint32_t so = sb + st * GH_STAGE;
#pragma unroll
        for (int arr = 0; arr < 2; arr++) {
            const __half* src = (arr == 0) ? Ah : Bh;
            const int base = (arr == 0) ? bm : bn;
#pragma unroll
            for (int i = 0; i < 2; i++) {
                const int idx = tid + i * 256;
                const int r = idx >> 2, kc = idx & 3;
                const void* g = src + (size_t)(base + r) * K + k0 + kc * 8;
                CP_ASYNC16(so + arr * GH_ARR + r * 80 + kc * 16, g);
            }
        }
    };

    load_stage(0, 0); CP_COMMIT();
    load_stage(1, 1); CP_COMMIT();

    float acc[4][4][4];
#pragma unroll
    for (int a = 0; a < 4; a++)
#pragma unroll
        for (int b = 0; b < 4; b++)
#pragma unroll
            for (int c = 0; c < 4; c++) acc[a][b][c] = 0.f;

    for (int kt = 0; kt < NT; kt++) {
        CP_WAIT1();
        __syncthreads();
        if (kt + 2 < NT) load_stage((kt + 2) % 3, kt + 2);
        CP_COMMIT();

        const uint32_t s0 = sb + (kt % 3) * GH_STAGE;
#pragma unroll
        for (int kh = 0; kh < 2; kh++) {
            uint32_t a_f[4][4], b_f[2][4];
#pragma unroll
            for (int mt = 0; mt < 4; mt++) {
                const int row = warp_m * 64 + mt * 16 + (lane & 15);
                const int chunk = kh * 2 + (lane >> 4);
                LDSM_X4(a_f[mt], s0 + row * 80 + chunk * 16);
            }
#pragma unroll
            for (int nt = 0; nt < 2; nt++) {
                const int row = warp_n * 32 + nt * 16 + (lane & 7) + ((lane >> 4) << 3);
                const int chunk = kh * 2 + ((lane >> 3) & 1);
                LDSM_X4(b_f[nt], s0 + GH_ARR + row * 80 + chunk * 16);
            }
#pragma unroll
            for (int mt = 0; mt < 4; mt++)
#pragma unroll
                for (int j = 0; j < 4; j++)
                    MMA16816(acc[mt][j], a_f[mt],
                             b_f[j >> 1][(j & 1) * 2], b_f[j >> 1][(j & 1) * 2 + 1]);
        }
    }

    const int gq = lane >> 2, tq = lane & 3;
#pragma unroll
    for (int mt = 0; mt < 4; mt++) {
#pragma unroll
        for (int j = 0; j < 4; j++) {
            const int col = bn + warp_n * 32 + j * 8 + tq * 2;
            float2 bb = make_float2(0.f, 0.f);
            if (EPI == 2 || EPI == 3) bb = *(const float2*)&bias[col];
#pragma unroll
            for (int rr = 0; rr < 2; rr++) {
                const int row = bm + warp_m * 64 + mt * 16 + gq + rr * 8;
                float vx = acc[mt][j][rr * 2 + 0];
                float vy = acc[mt][j][rr * 2 + 1];
                if (EPI == 2 || EPI == 3) { vx += bb.x; vy += bb.y; }
                if (EPI == 2) { vx = gelu_exact(vx); vy = gelu_exact(vy); }
                if (EPI == 1 || EPI == 3) {
                    const float2 rv = *(const float2*)&res[(size_t)row * N + col];
                    vx += rv.x; vy += rv.y;
                }
                if (OUTMODE == 2) {
                    *(__half2*)&Ch[(size_t)row * N + col] = __floats2half2_rn(vx, vy);
                } else {
                    *(float2*)&C[(size_t)row * N + col] = make_float2(vx, vy);
                }
            }
        }
    }
}

// ---------------------------------------------------------------------------
// HMMA flash attention. Grid (T/64, H, B), 128 threads = 4 warps.
// ---------------------------------------------------------------------------
#define AQ_S 72
#define ATT_Q     0
#define ATT_K(s)  (4608 + (s) * 4608)
#define ATT_V(s)  (13824 + (s) * 4608)
#define ATT_SMEM  (23040 * 2)

__global__ __launch_bounds__(128, 3)
void attn_hmma(const __half* __restrict__ qkv, __half* __restrict__ ao) {
    extern __shared__ __half sh[];
    const uint32_t sb = smem_u32(sh);
    const int tid = threadIdx.x;
    const int lane = tid & 31, w = tid >> 5;
    const int b = blockIdx.z, h = blockIdx.y, qt = blockIdx.x;
    const int hoff = h * DHEAD;
    const int rowbase = b * TSEQ + qt * 64;

#pragma unroll
    for (int p = 0; p < 4; p++) {
        const int idx = tid + p * 128;
        const int r = idx >> 3, c8 = idx & 7;
        *(uint4*)(sh + ATT_Q + r * AQ_S + c8 * 8) =
            *(const uint4*)(qkv + (size_t)(rowbase + r) * 3072 + hoff + c8 * 8);
    }

    auto load_kv = [&](int st, int kt) {
        const int kvbase = b * TSEQ + kt * 64;
#pragma unroll
        for (int p = 0; p < 4; p++) {
            const int idx = tid + p * 128;
            const int r = idx >> 3, c8 = idx & 7;
            const __half* gk = qkv + (size_t)(kvbase + r) * 3072 + 1024 + hoff + c8 * 8;
            CP_ASYNC16(sb + 2 * (ATT_K(st) + r * AQ_S + c8 * 8), gk);
            CP_ASYNC16(sb + 2 * (ATT_V(st) + r * AQ_S + c8 * 8), gk + 1024);
        }
    };

    load_kv(0, 0); CP_COMMIT();
    __syncthreads();

    uint32_t qa[4][4];
    const int m0 = w * 16;
#pragma unroll
    for (int kk = 0; kk < 4; kk++) {
        const uint32_t ad = sb + 2 * (ATT_Q + (m0 + (lane & 15)) * AQ_S +
                                      kk * 16 + (lane >> 4) * 8);
        LDSM_X4(qa[kk], ad);
    }

    float m_[2] = {-1e30f, -1e30f}, l_[2] = {0.f, 0.f};
    float o[8][4];
#pragma unroll
    for (int n = 0; n < 8; n++)
#pragma unroll
        for (int j = 0; j < 4; j++) o[n][j] = 0.f;

    const int NT = TSEQ / 64;
    for (int kt = 0; kt < NT; kt++) {
        __syncthreads();
        if (kt + 1 < NT) load_kv((kt + 1) & 1, kt + 1);
        CP_COMMIT();
        CP_WAIT1();
        __syncthreads();
        const int s = kt & 1;

        float c[8][4];
#pragma unroll
        for (int n = 0; n < 8; n++)
#pragma unroll
            for (int j = 0; j < 4; j++) c[n][j] = 0.f;

#pragma unroll
        for (int kk2 = 0; kk2 < 2; kk2++) {
#pragma unroll
            for (int n = 0; n < 8; n++) {
                uint32_t bf[4];
                const uint32_t ad = sb + 2 * (ATT_K(s) + (n * 8 + (lane & 7)) * AQ_S +
                                              kk2 * 32 + (lane >> 3) * 8);
                LDSM_X4(bf, ad);
                MMA16816(c[n], qa[2 * kk2], bf[0], bf[1]);
                MMA16816(c[n], qa[2 * kk2 + 1], bf[2], bf[3]);
            }
        }

        float tm0 = -1e30f, tm1 = -1e30f;
#pragma unroll
        for (int n = 0; n < 8; n++) {
            tm0 = fmaxf(tm0, fmaxf(c[n][0], c[n][1]));
            tm1 = fmaxf(tm1, fmaxf(c[n][2], c[n][3]));
        }
#pragma unroll
        for (int ofs = 1; ofs <= 2; ofs <<= 1) {
            tm0 = fmaxf(tm0, __shfl_xor_sync(0xffffffffu, tm0, ofs));
            tm1 = fmaxf(tm1, __shfl_xor_sync(0xffffffffu, tm1, ofs));
        }
        tm0 *= 0.125f; tm1 *= 0.125f;
        const float mn0 = fmaxf(m_[0], tm0), mn1 = fmaxf(m_[1], tm1);
        const float al0 = __expf(m_[0] - mn0), al1 = __expf(m_[1] - mn1);
        m_[0] = mn0; m_[1] = mn1;

        uint32_t u01[8], u23[8];
        float rs0 = 0.f, rs1 = 0.f;
#pragma unroll
        for (int n = 0; n < 8; n++) {
            const float p0 = __expf(c[n][0] * 0.125f - mn0);
            const float p1 = __expf(c[n][1] * 0.125f - mn0);
            const float p2 = __expf(c[n][2] * 0.125f - mn1);
            const float p3 = __expf(c[n][3] * 0.125f - mn1);
            rs0 += p0 + p1; rs1 += p2 + p3;
            const __half2 h01 = __floats2half2_rn(p0, p1);
            const __half2 h23 = __floats2half2_rn(p2, p3);
            u01[n] = *(const uint32_t*)&h01;
            u23[n] = *(const uint32_t*)&h23;
        }
#pragma unroll
        for (int ofs = 1; ofs <= 2; ofs <<= 1) {
            rs0 += __shfl_xor_sync(0xffffffffu, rs0, ofs);
            rs1 += __shfl_xor_sync(0xffffffffu, rs1, ofs);
        }
        l_[0] = l_[0] * al0 + rs0;
        l_[1] = l_[1] * al1 + rs1;
#pragma unroll
        for (int n = 0; n < 8; n++) {
            o[n][0] *= al0; o[n][1] *= al0;
            o[n][2] *= al1; o[n][3] *= al1;
        }

#pragma unroll
        for (int kk = 0; kk < 4; kk++) {
            uint32_t au[4] = {u01[2 * kk], u23[2 * kk], u01[2 * kk + 1], u23[2 * kk + 1]};
#pragma unroll
            for (int n2 = 0; n2 < 4; n2++) {
                uint32_t bf[4];
                const uint32_t ad = sb + 2 * (ATT_V(s) + (kk * 16 + (lane & 15)) * AQ_S +
                                              n2 * 16 + (lane >> 4) * 8);
                LDSM_X4_T(bf, ad);
                MMA16816(o[2 * n2], au, bf[0], bf[1]);
                MMA16816(o[2 * n2 + 1], au, bf[2], bf[3]);
            }
        }
    }

    const float inv0 = 1.0f / l_[0], inv1 = 1.0f / l_[1];
    const int r0 = lane >> 2, tq = lane & 3;
    const int grow0 = rowbase + m0 + r0, grow1 = grow0 + 8;
#pragma unroll
    for (int n = 0; n < 8; n++) {
        const int col = hoff + n * 8 + tq * 2;
        *(__half2*)&ao[(size_t)grow0 * DMODEL + col] =
            __floats2half2_rn(o[n][0] * inv0, o[n][1] * inv0);
        *(__half2*)&ao[(size_t)grow1 * DMODEL + col] =
            __floats2half2_rn(o[n][2] * inv1, o[n][3] * inv1);
    }
}

// ---------------------------------------------------------------------------
// Launcher
// ---------------------------------------------------------------------------
extern "C" void kernel_launch(void* const* d_in, const int* in_sizes, int n_in,
                              void* d_out, int out_size) {
    const float* x     = (const float*)d_in[0];
    const float* ln1_s = (const float*)d_in[1];
    const float* ln1_b = (const float*)d_in[2];
    const float* qkv_w = (const float*)d_in[3];
    const float* out_w = (const float*)d_in[4];
    const float* ln2_s = (const float*)d_in[5];
    const float* ln2_b = (const float*)d_in[6];
    const float* fc1_w = (const float*)d_in[7];
    const float* fc1_b = (const float*)d_in[8];
    const float* fc2_w = (const float*)d_in[9];
    const float* fc2_b = (const float*)d_in[10];
    float* out = (float*)d_out;

    float *x1_p;
    __half *qkvh, *act, *ff, *wq, *wo, *w1, *w2;
    cudaGetSymbolAddress((void**)&x1_p, g_x1);
    cudaGetSymbolAddress((void**)&qkvh, g_qkvh);
    cudaGetSymbolAddress((void**)&act, g_act);
    cudaGetSymbolAddress((void**)&ff, g_ff);
    cudaGetSymbolAddress((void**)&wq, g_wqkv);
    cudaGetSymbolAddress((void**)&wo, g_wout);
    cudaGetSymbolAddress((void**)&w1, g_wfc1);
    cudaGetSymbolAddress((void**)&w2, g_wfc2);

    cudaFuncSetAttribute(gemm_hmma<0, 2>, cudaFuncAttributeMaxDynamicSharedMemorySize, GH_SMEM);
    cudaFuncSetAttribute(gemm_hmma<1, 0>, cudaFuncAttributeMaxDynamicSharedMemorySize, GH_SMEM);
    cudaFuncSetAttribute(gemm_hmma<2, 2>, cudaFuncAttributeMaxDynamicSharedMemorySize, GH_SMEM);
    cudaFuncSetAttribute(gemm_hmma<3, 0>, cudaFuncAttributeMaxDynamicSharedMemorySize, GH_SMEM);

    // 0) Weight prep: fp32 -> fp16
    cvt_kernel<<<3 * DMODEL * DMODEL / 4 / 256, 256>>>(qkv_w, wq, 3 * DMODEL * DMODEL / 4);
    cvt_kernel<<<DMODEL * DMODEL / 4 / 256, 256>>>(out_w, wo, DMODEL * DMODEL / 4);
    cvt_kernel<<<DFF * DMODEL / 4 / 256, 256>>>(fc1_w, w1, DFF * DMODEL / 4);
    cvt_kernel<<<DMODEL * DFF / 4 / 256, 256>>>(fc2_w, w2, DMODEL * DFF / 4);

    // 1) LN1 -> fp16 activations
    ln_kernel<<<MROWS, 256>>>(x, ln1_s, ln1_b, act);

    // 2) QKV projection -> fp16
    gemm_hmma<0, 2><<<dim3(3 * DMODEL / 128, MROWS / 128), 256, GH_SMEM>>>(
        act, wq, nullptr, qkvh, MROWS, 3 * DMODEL, DMODEL, nullptr, nullptr);

    // 3) HMMA flash attention -> fp16
    attn_hmma<<<dim3(TSEQ / 64, NHEAD, BATCH), 128, ATT_SMEM>>>(qkvh, act);

    // 4) Out projection + residual -> x1 fp32
    gemm_hmma<1, 0><<<dim3(DMODEL / 128, MROWS / 128), 256, GH_SMEM>>>(
        act, wo, x1_p, nullptr, MROWS, DMODEL, DMODEL, nullptr, x);

    // 5) LN2 -> fp16 activations
    ln_kernel<<<MROWS, 256>>>(x1_p, ln2_s, ln2_b, act);

    // 6) FC1 + bias + GELU -> fp16
    gemm_hmma<2, 2><<<dim3(DFF / 128, MROWS / 128), 256, GH_SMEM>>>(
        act, w1, nullptr, ff, MROWS, DFF, DMODEL, fc1_b, nullptr);

    // 7) FC2 + bias + residual -> out fp32
    gemm_hmma<3, 0><<<dim3(DMODEL / 128, MROWS / 128), 256, GH_SMEM>>>(
        ff, w2, out, nullptr, MROWS, DMODEL, DFF, fc2_b, x1_p);
}

// round 8
// speedup vs baseline: 7.1506x; 1.1084x over previous
#include <cuda_runtime.h>
#include <cuda_fp16.h>
#include <math.h>
#include <stdint.h>

// Problem constants
#define BATCH 4
#define TSEQ 2048
#define DMODEL 1024
#define NHEAD 16
#define DHEAD 64
#define DFF 4096
#define MROWS (BATCH * TSEQ)   // 8192

// ---------------------------------------------------------------------------
// Scratch (device globals; no runtime allocation allowed)
// ---------------------------------------------------------------------------
__device__ float  g_x1[(size_t)MROWS * DMODEL];
__device__ __half g_qkvh[(size_t)MROWS * 3 * DMODEL];
__device__ __half g_act[(size_t)MROWS * DMODEL];
__device__ __half g_ff[(size_t)MROWS * DFF];
__device__ __half g_wqkv[(size_t)3 * DMODEL * DMODEL];
__device__ __half g_wout[(size_t)DMODEL * DMODEL];
__device__ __half g_wfc1[(size_t)DFF * DMODEL];
__device__ __half g_wfc2[(size_t)DMODEL * DFF];

// ---------------------------------------------------------------------------
// Helpers
// ---------------------------------------------------------------------------
__device__ __forceinline__ uint32_t smem_u32(const void* p) {
    uint32_t a;
    asm("{ .reg .u64 t; cvta.to.shared.u64 t, %1; cvt.u32.u64 %0, t; }"
        : "=r"(a) : "l"(p));
    return a;
}

#define LDSM_X4(d, a)                                                        \
    asm volatile("ldmatrix.sync.aligned.m8n8.x4.shared.b16 "                 \
                 "{%0,%1,%2,%3}, [%4];"                                      \
                 : "=r"((d)[0]), "=r"((d)[1]), "=r"((d)[2]), "=r"((d)[3])    \
                 : "r"(a))

#define LDSM_X4_T(d, a)                                                      \
    asm volatile("ldmatrix.sync.aligned.m8n8.x4.trans.shared.b16 "           \
                 "{%0,%1,%2,%3}, [%4];"                                      \
                 : "=r"((d)[0]), "=r"((d)[1]), "=r"((d)[2]), "=r"((d)[3])    \
                 : "r"(a))

#define MMA16816(c, a, b0, b1)                                               \
    asm volatile("mma.sync.aligned.m16n8k16.row.col.f32.f16.f16.f32 "        \
                 "{%0,%1,%2,%3},{%4,%5,%6,%7},{%8,%9},{%0,%1,%2,%3};"        \
                 : "+f"((c)[0]), "+f"((c)[1]), "+f"((c)[2]), "+f"((c)[3])    \
                 : "r"((a)[0]), "r"((a)[1]), "r"((a)[2]), "r"((a)[3]),       \
                   "r"(b0), "r"(b1))

#define CP_ASYNC16(s, g) \
    asm volatile("cp.async.cg.shared.global [%0], [%1], 16;" :: "r"(s), "l"(g))
#define CP_COMMIT() asm volatile("cp.async.commit_group;")
#define CP_WAIT1()  asm volatile("cp.async.wait_group 1;")

__device__ __forceinline__ float gelu_exact(float x) {
    return 0.5f * x * (1.0f + erff(x * 0.70710678118654752f));
}

// ---------------------------------------------------------------------------
// Weight convert: fp32 -> fp16
// ---------------------------------------------------------------------------
__global__ __launch_bounds__(256)
void cvt_kernel(const float* __restrict__ in, __half* __restrict__ hi, int n4) {
    const int i = blockIdx.x * 256 + threadIdx.x;
    if (i >= n4) return;
    const float4 v = ((const float4*)in)[i];
    ((__half2*)hi)[i * 2 + 0] = __floats2half2_rn(v.x, v.y);
    ((__half2*)hi)[i * 2 + 1] = __floats2half2_rn(v.z, v.w);
}

// ---------------------------------------------------------------------------
// LayerNorm -> single fp16
// ---------------------------------------------------------------------------
__global__ __launch_bounds__(256)
void ln_kernel(const float* __restrict__ x, const float* __restrict__ sc,
               const float* __restrict__ bi, __half* __restrict__ y) {
    const int row = blockIdx.x;
    const int t = threadIdx.x;
    const float4 v = *(const float4*)(x + (size_t)row * DMODEL + t * 4);
    float s = v.x + v.y + v.z + v.w;
    float s2 = v.x * v.x + v.y * v.y + v.z * v.z + v.w * v.w;
#pragma unroll
    for (int o = 16; o; o >>= 1) {
        s  += __shfl_xor_sync(0xffffffffu, s, o);
        s2 += __shfl_xor_sync(0xffffffffu, s2, o);
    }
    __shared__ float rs[8], rs2[8];
    if ((t & 31) == 0) { rs[t >> 5] = s; rs2[t >> 5] = s2; }
    __syncthreads();
    s = 0.f; s2 = 0.f;
#pragma unroll
    for (int i = 0; i < 8; i++) { s += rs[i]; s2 += rs2[i]; }
    const float mu = s * (1.0f / DMODEL);
    const float var = s2 * (1.0f / DMODEL) - mu * mu;
    const float r = rsqrtf(var + 1e-5f);
    const float4 g4 = *(const float4*)(sc + t * 4);
    const float4 b4 = *(const float4*)(bi + t * 4);
    float4 o4;
    o4.x = (v.x - mu) * r * g4.x + b4.x;
    o4.y = (v.y - mu) * r * g4.y + b4.y;
    o4.z = (v.z - mu) * r * g4.z + b4.z;
    o4.w = (v.w - mu) * r * g4.w + b4.w;
    const size_t off = (size_t)row * DMODEL + t * 4;
    ((__half2*)(y + off))[0] = __floats2half2_rn(o4.x, o4.y);
    ((__half2*)(y + off))[1] = __floats2half2_rn(o4.z, o4.w);
}

// ---------------------------------------------------------------------------
// HMMA fp16 GEMM: C[M,N] = A[M,K] @ W[N,K]^T, fp32 accumulate.
//   EPI 0: none | 1: +res | 2: +bias,GELU | 3: +bias+res
//   OUTMODE 0: fp32 C | 2: single fp16 Ch
// CTA tile 128x128, BK=64, 8 warps (64x32), 2-stage cp.async, 2 CTAs/SM.
// Row stride 144 B (64 halfs + 8 pad) -> conflict-free ldmatrix.
// smem: 2 stages x 2 arrays x 128 rows x 144B = 73728 B
// ---------------------------------------------------------------------------
#define GH_ROWB  144
#define GH_ARR   (128 * GH_ROWB)       // 18432
#define GH_STAGE (2 * GH_ARR)          // 36864
#define GH_SMEM  (2 * GH_STAGE)        // 73728

template <int EPI, int OUTMODE>
__global__ __launch_bounds__(256, 2)
void gemm_hmma(const __half* __restrict__ Ah, const __half* __restrict__ Bh,
               float* __restrict__ C, __half* __restrict__ Ch,
               int M, int N, int K,
               const float* __restrict__ bias, const float* __restrict__ res) {
    extern __shared__ char sm[];
    const uint32_t sb = smem_u32(sm);
    const int tid = threadIdx.x;
    const int lane = tid & 31, wid = tid >> 5;
    const int warp_m = wid >> 2, warp_n = wid & 3;
    const int bm = blockIdx.y * 128, bn = blockIdx.x * 128;
    const int NT = K >> 6;   // K tiles of 64

    auto load_stage = [&](int st, int kt) {
        const int k0 = kt * 64;
        const uint32_t so = sb + st * GH_STAGE;
#pragma unroll
        for (int arr = 0; arr < 2; arr++) {
            const __half* src = (arr == 0) ? Ah : Bh;
            const int base = (arr == 0) ? bm : bn;
#pragma unroll
            for (int i = 0; i < 4; i++) {
                const int idx = tid + i * 256;
                const int r = idx >> 3, kc = idx & 7;
                const void* g = src + (size_t)(base + r) * K + k0 + kc * 8;
                CP_ASYNC16(so + arr * GH_ARR + r * GH_ROWB + kc * 16, g);
            }
        }
    };

    load_stage(0, 0); CP_COMMIT();

    float acc[4][4][4];
#pragma unroll
    for (int a = 0; a < 4; a++)
#pragma unroll
        for (int b = 0; b < 4; b++)
#pragma unroll
            for (int c = 0; c < 4; c++) acc[a][b][c] = 0.f;

    for (int kt = 0; kt < NT; kt++) {
        if (kt + 1 < NT) load_stage((kt + 1) & 1, kt + 1);
        CP_COMMIT();
        CP_WAIT1();
        __syncthreads();

        const uint32_t s0 = sb + (kt & 1) * GH_STAGE;
#pragma unroll
        for (int kh = 0; kh < 4; kh++) {
            uint32_t a_f[4][4], b_f[2][4];
#pragma unroll
            for (int mt = 0; mt < 4; mt++) {
                const int row = warp_m * 64 + mt * 16 + (lane & 15);
                LDSM_X4(a_f[mt], s0 + row * GH_ROWB + kh * 32 + (lane >> 4) * 16);
            }
#pragma unroll
            for (int nt = 0; nt < 2; nt++) {
                const int row = warp_n * 32 + nt * 16 + (lane & 7) + ((lane >> 4) << 3);
                LDSM_X4(b_f[nt], s0 + GH_ARR + row * GH_ROWB + kh * 32 +
                                 ((lane >> 3) & 1) * 16);
            }
#pragma unroll
            for (int mt = 0; mt < 4; mt++)
#pragma unroll
                for (int j = 0; j < 4; j++)
                    MMA16816(acc[mt][j], a_f[mt],
                             b_f[j >> 1][(j & 1) * 2], b_f[j >> 1][(j & 1) * 2 + 1]);
        }
        __syncthreads();
    }

    const int gq = lane >> 2, tq = lane & 3;
#pragma unroll
    for (int mt = 0; mt < 4; mt++) {
#pragma unroll
        for (int j = 0; j < 4; j++) {
            const int col = bn + warp_n * 32 + j * 8 + tq * 2;
            float2 bb = make_float2(0.f, 0.f);
            if (EPI == 2 || EPI == 3) bb = *(const float2*)&bias[col];
#pragma unroll
            for (int rr = 0; rr < 2; rr++) {
                const int row = bm + warp_m * 64 + mt * 16 + gq + rr * 8;
                float vx = acc[mt][j][rr * 2 + 0];
                float vy = acc[mt][j][rr * 2 + 1];
                if (EPI == 2 || EPI == 3) { vx += bb.x; vy += bb.y; }
                if (EPI == 2) { vx = gelu_exact(vx); vy = gelu_exact(vy); }
                if (EPI == 1 || EPI == 3) {
                    const float2 rv = *(const float2*)&res[(size_t)row * N + col];
                    vx += rv.x; vy += rv.y;
                }
                if (OUTMODE == 2) {
                    *(__half2*)&Ch[(size_t)row * N + col] = __floats2half2_rn(vx, vy);
                } else {
                    *(float2*)&C[(size_t)row * N + col] = make_float2(vx, vy);
                }
            }
        }
    }
}

// ---------------------------------------------------------------------------
// HMMA flash attention. Grid (T/128, H, B), 128 threads = 4 warps.
// 128-row Q tile; each warp owns 32 q-rows (two 16-row MMA groups).
// K/V tiles 64x64 fp16, cp.async double buffer. V-frags shared across groups.
// ---------------------------------------------------------------------------
#define AQ_S 72
#define ATT_Q     0
#define ATT_K(s)  (9216 + (s) * 4608)
#define ATT_V(s)  (18432 + (s) * 4608)
#define ATT_SMEM  (27648 * 2)          // 55296 B

__global__ __launch_bounds__(128, 2)
void attn_hmma(const __half* __restrict__ qkv, __half* __restrict__ ao) {
    extern __shared__ __half sh[];
    const uint32_t sb = smem_u32(sh);
    const int tid = threadIdx.x;
    const int lane = tid & 31, w = tid >> 5;
    const int b = blockIdx.z, h = blockIdx.y, qt = blockIdx.x;
    const int hoff = h * DHEAD;
    const int rowbase = b * TSEQ + qt * 128;

    // Load Q tile (128 rows x 64 halfs)
#pragma unroll
    for (int p = 0; p < 8; p++) {
        const int idx = tid + p * 128;
        const int r = idx >> 3, c8 = idx & 7;
        *(uint4*)(sh + ATT_Q + r * AQ_S + c8 * 8) =
            *(const uint4*)(qkv + (size_t)(rowbase + r) * 3072 + hoff + c8 * 8);
    }

    auto load_kv = [&](int st, int kt) {
        const int kvbase = b * TSEQ + kt * 64;
#pragma unroll
        for (int p = 0; p < 4; p++) {
            const int idx = tid + p * 128;
            const int r = idx >> 3, c8 = idx & 7;
            const __half* gk = qkv + (size_t)(kvbase + r) * 3072 + 1024 + hoff + c8 * 8;
            CP_ASYNC16(sb + 2 * (ATT_K(st) + r * AQ_S + c8 * 8), gk);
            CP_ASYNC16(sb + 2 * (ATT_V(st) + r * AQ_S + c8 * 8), gk + 1024);
        }
    };

    load_kv(0, 0); CP_COMMIT();
    __syncthreads();

    // Preload Q A-fragments: 2 row-groups x 4 k-steps
    uint32_t qa[2][4][4];
    const int m0 = w * 32;
#pragma unroll
    for (int mt = 0; mt < 2; mt++)
#pragma unroll
        for (int kk = 0; kk < 4; kk++) {
            const uint32_t ad = sb + 2 * (ATT_Q + (m0 + mt * 16 + (lane & 15)) * AQ_S +
                                          kk * 16 + (lane >> 4) * 8);
            LDSM_X4(qa[mt][kk], ad);
        }

    float m_[2][2], l_[2][2];
    float o[2][8][4];
#pragma unroll
    for (int mt = 0; mt < 2; mt++) {
        m_[mt][0] = -1e30f; m_[mt][1] = -1e30f;
        l_[mt][0] = 0.f;    l_[mt][1] = 0.f;
#pragma unroll
        for (int n = 0; n < 8; n++)
#pragma unroll
            for (int j = 0; j < 4; j++) o[mt][n][j] = 0.f;
    }

    const int NT = TSEQ / 64;
    for (int kt = 0; kt < NT; kt++) {
        __syncthreads();
        if (kt + 1 < NT) load_kv((kt + 1) & 1, kt + 1);
        CP_COMMIT();
        CP_WAIT1();
        __syncthreads();
        const int s = kt & 1;

        // ---- S = Q K^T (both row-groups share each K fragment) ----
        float c[2][8][4];
#pragma unroll
        for (int mt = 0; mt < 2; mt++)
#pragma unroll
            for (int n = 0; n < 8; n++)
#pragma unroll
                for (int j = 0; j < 4; j++) c[mt][n][j] = 0.f;

#pragma unroll
        for (int kk2 = 0; kk2 < 2; kk2++) {
#pragma unroll
            for (int n = 0; n < 8; n++) {
                uint32_t bf[4];
                const uint32_t ad = sb + 2 * (ATT_K(s) + (n * 8 + (lane & 7)) * AQ_S +
                                              kk2 * 32 + (lane >> 3) * 8);
                LDSM_X4(bf, ad);
#pragma unroll
                for (int mt = 0; mt < 2; mt++) {
                    MMA16816(c[mt][n], qa[mt][2 * kk2], bf[0], bf[1]);
                    MMA16816(c[mt][n], qa[mt][2 * kk2 + 1], bf[2], bf[3]);
                }
            }
        }

        // ---- online softmax per row-group ----
        uint32_t u01[2][8], u23[2][8];
#pragma unroll
        for (int mt = 0; mt < 2; mt++) {
            float tm0 = -1e30f, tm1 = -1e30f;
#pragma unroll
            for (int n = 0; n < 8; n++) {
                tm0 = fmaxf(tm0, fmaxf(c[mt][n][0], c[mt][n][1]));
                tm1 = fmaxf(tm1, fmaxf(c[mt][n][2], c[mt][n][3]));
            }
#pragma unroll
            for (int ofs = 1; ofs <= 2; ofs <<= 1) {
                tm0 = fmaxf(tm0, __shfl_xor_sync(0xffffffffu, tm0, ofs));
                tm1 = fmaxf(tm1, __shfl_xor_sync(0xffffffffu, tm1, ofs));
            }
            tm0 *= 0.125f; tm1 *= 0.125f;
            const float mn0 = fmaxf(m_[mt][0], tm0), mn1 = fmaxf(m_[mt][1], tm1);
            const float al0 = __expf(m_[mt][0] - mn0), al1 = __expf(m_[mt][1] - mn1);
            m_[mt][0] = mn0; m_[mt][1] = mn1;

            float rs0 = 0.f, rs1 = 0.f;
#pragma unroll
            for (int n = 0; n < 8; n++) {
                const float p0 = __expf(c[mt][n][0] * 0.125f - mn0);
                const float p1 = __expf(c[mt][n][1] * 0.125f - mn0);
                const float p2 = __expf(c[mt][n][2] * 0.125f - mn1);
                const float p3 = __expf(c[mt][n][3] * 0.125f - mn1);
                rs0 += p0 + p1; rs1 += p2 + p3;
                const __half2 h01 = __floats2half2_rn(p0, p1);
                const __half2 h23 = __floats2half2_rn(p2, p3);
                u01[mt][n] = *(const uint32_t*)&h01;
                u23[mt][n] = *(const uint32_t*)&h23;
            }
#pragma unroll
            for (int ofs = 1; ofs <= 2; ofs <<= 1) {
                rs0 += __shfl_xor_sync(0xffffffffu, rs0, ofs);
                rs1 += __shfl_xor_sync(0xffffffffu, rs1, ofs);
            }
            l_[mt][0] = l_[mt][0] * al0 + rs0;
            l_[mt][1] = l_[mt][1] * al1 + rs1;
#pragma unroll
            for (int n = 0; n < 8; n++) {
                o[mt][n][0] *= al0; o[mt][n][1] *= al0;
                o[mt][n][2] *= al1; o[mt][n][3] *= al1;
            }
        }

        // ---- O += P V (V fragments shared across row-groups) ----
#pragma unroll
        for (int kk = 0; kk < 4; kk++) {
            uint32_t au0[4] = {u01[0][2 * kk], u23[0][2 * kk],
                               u01[0][2 * kk + 1], u23[0][2 * kk + 1]};
            uint32_t au1[4] = {u01[1][2 * kk], u23[1][2 * kk],
                               u01[1][2 * kk + 1], u23[1][2 * kk + 1]};
#pragma unroll
            for (int n2 = 0; n2 < 4; n2++) {
                uint32_t bf[4];
                const uint32_t ad = sb + 2 * (ATT_V(s) + (kk * 16 + (lane & 15)) * AQ_S +
                                              n2 * 16 + (lane >> 4) * 8);
                LDSM_X4_T(bf, ad);
                MMA16816(o[0][2 * n2], au0, bf[0], bf[1]);
                MMA16816(o[0][2 * n2 + 1], au0, bf[2], bf[3]);
                MMA16816(o[1][2 * n2], au1, bf[0], bf[1]);
                MMA16816(o[1][2 * n2 + 1], au1, bf[2], bf[3]);
            }
        }
    }

    // ---- epilogue ----
    const int r0 = lane >> 2, tq = lane & 3;
#pragma unroll
    for (int mt = 0; mt < 2; mt++) {
        const float inv0 = 1.0f / l_[mt][0], inv1 = 1.0f / l_[mt][1];
        const int grow0 = rowbase + m0 + mt * 16 + r0, grow1 = grow0 + 8;
#pragma unroll
        for (int n = 0; n < 8; n++) {
            const int col = hoff + n * 8 + tq * 2;
            *(__half2*)&ao[(size_t)grow0 * DMODEL + col] =
                __floats2half2_rn(o[mt][n][0] * inv0, o[mt][n][1] * inv0);
            *(__half2*)&ao[(size_t)grow1 * DMODEL + col] =
                __floats2half2_rn(o[mt][n][2] * inv1, o[mt][n][3] * inv1);
        }
    }
}

// ---------------------------------------------------------------------------
// Launcher
// ---------------------------------------------------------------------------
extern "C" void kernel_launch(void* const* d_in, const int* in_sizes, int n_in,
                              void* d_out, int out_size) {
    const float* x     = (const float*)d_in[0];
    const float* ln1_s = (const float*)d_in[1];
    const float* ln1_b = (const float*)d_in[2];
    const float* qkv_w = (const float*)d_in[3];
    const float* out_w = (const float*)d_in[4];
    const float* ln2_s = (const float*)d_in[5];
    const float* ln2_b = (const float*)d_in[6];
    const float* fc1_w = (const float*)d_in[7];
    const float* fc1_b = (const float*)d_in[8];
    const float* fc2_w = (const float*)d_in[9];
    const float* fc2_b = (const float*)d_in[10];
    float* out = (float*)d_out;

    float *x1_p;
    __half *qkvh, *act, *ff, *wq, *wo, *w1, *w2;
    cudaGetSymbolAddress((void**)&x1_p, g_x1);
    cudaGetSymbolAddress((void**)&qkvh, g_qkvh);
    cudaGetSymbolAddress((void**)&act, g_act);
    cudaGetSymbolAddress((void**)&ff, g_ff);
    cudaGetSymbolAddress((void**)&wq, g_wqkv);
    cudaGetSymbolAddress((void**)&wo, g_wout);
    cudaGetSymbolAddress((void**)&w1, g_wfc1);
    cudaGetSymbolAddress((void**)&w2, g_wfc2);

    cudaFuncSetAttribute(gemm_hmma<0, 2>, cudaFuncAttributeMaxDynamicSharedMemorySize, GH_SMEM);
    cudaFuncSetAttribute(gemm_hmma<1, 0>, cudaFuncAttributeMaxDynamicSharedMemorySize, GH_SMEM);
    cudaFuncSetAttribute(gemm_hmma<2, 2>, cudaFuncAttributeMaxDynamicSharedMemorySize, GH_SMEM);
    cudaFuncSetAttribute(gemm_hmma<3, 0>, cudaFuncAttributeMaxDynamicSharedMemorySize, GH_SMEM);
    cudaFuncSetAttribute(attn_hmma, cudaFuncAttributeMaxDynamicSharedMemorySize, ATT_SMEM);

    // 0) Weight prep: fp32 -> fp16
    cvt_kernel<<<3 * DMODEL * DMODEL / 4 / 256, 256>>>(qkv_w, wq, 3 * DMODEL * DMODEL / 4);
    cvt_kernel<<<DMODEL * DMODEL / 4 / 256, 256>>>(out_w, wo, DMODEL * DMODEL / 4);
    cvt_kernel<<<DFF * DMODEL / 4 / 256, 256>>>(fc1_w, w1, DFF * DMODEL / 4);
    cvt_kernel<<<DMODEL * DFF / 4 / 256, 256>>>(fc2_w, w2, DMODEL * DFF / 4);

    // 1) LN1 -> fp16 activations
    ln_kernel<<<MROWS, 256>>>(x, ln1_s, ln1_b, act);

    // 2) QKV projection -> fp16
    gemm_hmma<0, 2><<<dim3(3 * DMODEL / 128, MROWS / 128), 256, GH_SMEM>>>(
        act, wq, nullptr, qkvh, MROWS, 3 * DMODEL, DMODEL, nullptr, nullptr);

    // 3) HMMA flash attention -> fp16
    attn_hmma<<<dim3(TSEQ / 128, NHEAD, BATCH), 128, ATT_SMEM>>>(qkvh, act);

    // 4) Out projection + residual -> x1 fp32
    gemm_hmma<1, 0><<<dim3(DMODEL / 128, MROWS / 128), 256, GH_SMEM>>>(
        act, wo, x1_p, nullptr, MROWS, DMODEL, DMODEL, nullptr, x);

    // 5) LN2 -> fp16 activations
    ln_kernel<<<MROWS, 256>>>(x1_p, ln2_s, ln2_b, act);

    // 6) FC1 + bias + GELU -> fp16
    gemm_hmma<2, 2><<<dim3(DFF / 128, MROWS / 128), 256, GH_SMEM>>>(
        act, w1, nullptr, ff, MROWS, DFF, DMODEL, fc1_b, nullptr);

    // 7) FC2 + bias + residual -> out fp32
    gemm_hmma<3, 0><<<dim3(DMODEL / 128, MROWS / 128), 256, GH_SMEM>>>(
        ff, w2, out, nullptr, MROWS, DMODEL, DFF, fc2_b, x1_p);
}

// round 9
// speedup vs baseline: 7.4130x; 1.0367x over previous
#include <cuda_runtime.h>
#include <cuda_fp16.h>
#include <math.h>
#include <stdint.h>

// Problem constants
#define BATCH 4
#define TSEQ 2048
#define DMODEL 1024
#define NHEAD 16
#define DHEAD 64
#define DFF 4096
#define MROWS (BATCH * TSEQ)   // 8192

// ---------------------------------------------------------------------------
// Scratch (device globals; no runtime allocation allowed)
// ---------------------------------------------------------------------------
__device__ float  g_x1[(size_t)MROWS * DMODEL];
__device__ __half g_qkvh[(size_t)MROWS * 3 * DMODEL];
__device__ __half g_act[(size_t)MROWS * DMODEL];
__device__ __half g_ff[(size_t)MROWS * DFF];
__device__ __half g_wqkv[(size_t)3 * DMODEL * DMODEL];
__device__ __half g_wout[(size_t)DMODEL * DMODEL];
__device__ __half g_wfc1[(size_t)DFF * DMODEL];
__device__ __half g_wfc2[(size_t)DMODEL * DFF];

// ---------------------------------------------------------------------------
// Helpers
// ---------------------------------------------------------------------------
__device__ __forceinline__ uint32_t smem_u32(const void* p) {
    uint32_t a;
    asm("{ .reg .u64 t; cvta.to.shared.u64 t, %1; cvt.u32.u64 %0, t; }"
        : "=r"(a) : "l"(p));
    return a;
}

#define LDSM_X4(d, a)                                                        \
    asm volatile("ldmatrix.sync.aligned.m8n8.x4.shared.b16 "                 \
                 "{%0,%1,%2,%3}, [%4];"                                      \
                 : "=r"((d)[0]), "=r"((d)[1]), "=r"((d)[2]), "=r"((d)[3])    \
                 : "r"(a))

#define LDSM_X4_T(d, a)                                                      \
    asm volatile("ldmatrix.sync.aligned.m8n8.x4.trans.shared.b16 "           \
                 "{%0,%1,%2,%3}, [%4];"                                      \
                 : "=r"((d)[0]), "=r"((d)[1]), "=r"((d)[2]), "=r"((d)[3])    \
                 : "r"(a))

#define MMA16816(c, a, b0, b1)                                               \
    asm volatile("mma.sync.aligned.m16n8k16.row.col.f32.f16.f16.f32 "        \
                 "{%0,%1,%2,%3},{%4,%5,%6,%7},{%8,%9},{%0,%1,%2,%3};"        \
                 : "+f"((c)[0]), "+f"((c)[1]), "+f"((c)[2]), "+f"((c)[3])    \
                 : "r"((a)[0]), "r"((a)[1]), "r"((a)[2]), "r"((a)[3]),       \
                   "r"(b0), "r"(b1))

#define CP_ASYNC16(s, g) \
    asm volatile("cp.async.cg.shared.global [%0], [%1], 16;" :: "r"(s), "l"(g))
#define CP_COMMIT() asm volatile("cp.async.commit_group;")
#define CP_WAIT1()  asm volatile("cp.async.wait_group 1;")

__device__ __forceinline__ float gelu_exact(float x) {
    return 0.5f * x * (1.0f + erff(x * 0.70710678118654752f));
}

// ---------------------------------------------------------------------------
// Weight convert: fp32 -> fp16
// ---------------------------------------------------------------------------
__global__ __launch_bounds__(256)
void cvt_kernel(const float* __restrict__ in, __half* __restrict__ hi, int n4) {
    const int i = blockIdx.x * 256 + threadIdx.x;
    if (i >= n4) return;
    const float4 v = ((const float4*)in)[i];
    ((__half2*)hi)[i * 2 + 0] = __floats2half2_rn(v.x, v.y);
    ((__half2*)hi)[i * 2 + 1] = __floats2half2_rn(v.z, v.w);
}

// ---------------------------------------------------------------------------
// LayerNorm -> single fp16
// ---------------------------------------------------------------------------
__global__ __launch_bounds__(256)
void ln_kernel(const float* __restrict__ x, const float* __restrict__ sc,
               const float* __restrict__ bi, __half* __restrict__ y) {
    const int row = blockIdx.x;
    const int t = threadIdx.x;
    const float4 v = *(const float4*)(x + (size_t)row * DMODEL + t * 4);
    float s = v.x + v.y + v.z + v.w;
    float s2 = v.x * v.x + v.y * v.y + v.z * v.z + v.w * v.w;
#pragma unroll
    for (int o = 16; o; o >>= 1) {
        s  += __shfl_xor_sync(0xffffffffu, s, o);
        s2 += __shfl_xor_sync(0xffffffffu, s2, o);
    }
    __shared__ float rs[8], rs2[8];
    if ((t & 31) == 0) { rs[t >> 5] = s; rs2[t >> 5] = s2; }
    __syncthreads();
    s = 0.f; s2 = 0.f;
#pragma unroll
    for (int i = 0; i < 8; i++) { s += rs[i]; s2 += rs2[i]; }
    const float mu = s * (1.0f / DMODEL);
    const float var = s2 * (1.0f / DMODEL) - mu * mu;
    const float r = rsqrtf(var + 1e-5f);
    const float4 g4 = *(const float4*)(sc + t * 4);
    const float4 b4 = *(const float4*)(bi + t * 4);
    float4 o4;
    o4.x = (v.x - mu) * r * g4.x + b4.x;
    o4.y = (v.y - mu) * r * g4.y + b4.y;
    o4.z = (v.z - mu) * r * g4.z + b4.z;
    o4.w = (v.w - mu) * r * g4.w + b4.w;
    const size_t off = (size_t)row * DMODEL + t * 4;
    ((__half2*)(y + off))[0] = __floats2half2_rn(o4.x, o4.y);
    ((__half2*)(y + off))[1] = __floats2half2_rn(o4.z, o4.w);
}

// ---------------------------------------------------------------------------
// HMMA fp16 GEMM: C[M,N] = A[M,K] @ W[N,K]^T, fp32 accumulate.
//   EPI 0: none | 1: +res | 2: +bias,GELU | 3: +bias+res
//   OUTMODE 0: fp32 C | 2: single fp16 Ch
// CTA tile 128x256, warp tile 64x64 (8 warps as 2x4), BK=64,
// 3-stage cp.async ring, ONE barrier per k-tile, 1 CTA/SM.
// Row stride 144 B -> conflict-free ldmatrix (144 mod 128 = 16).
// smem: 3 stages x (128+256) rows x 144 B = 165888 B
// ---------------------------------------------------------------------------
#define GH_ROWB  144
#define GH_A_ARR (128 * GH_ROWB)           // 18432
#define GH_B_ARR (256 * GH_ROWB)           // 36864
#define GH_STAGE (GH_A_ARR + GH_B_ARR)     // 55296
#define GH_SMEM  (3 * GH_STAGE)            // 165888

template <int EPI, int OUTMODE>
__global__ __launch_bounds__(256, 1)
void gemm_hmma(const __half* __restrict__ Ah, const __half* __restrict__ Bh,
               float* __restrict__ C, __half* __restrict__ Ch,
               int M, int N, int K,
               const float* __restrict__ bias, const float* __restrict__ res) {
    extern __shared__ char sm[];
    const uint32_t sb = smem_u32(sm);
    const int tid = threadIdx.x;
    const int lane = tid & 31, wid = tid >> 5;
    const int warp_m = wid >> 2, warp_n = wid & 3;   // 2 x 4
    const int bm = blockIdx.y * 128, bn = blockIdx.x * 256;
    const int NT = K >> 6;   // K tiles of 64

    auto load_stage = [&](int st, int kt) {
        const int k0 = kt * 64;
        const uint32_t so = sb + st * GH_STAGE;
#pragma unroll
        for (int i = 0; i < 4; i++) {                 // A: 128 rows
            const int idx = tid + i * 256;
            const int r = idx >> 3, kc = idx & 7;
            CP_ASYNC16(so + r * GH_ROWB + kc * 16,
                       Ah + (size_t)(bm + r) * K + k0 + kc * 8);
        }
#pragma unroll
        for (int i = 0; i < 8; i++) {                 // B: 256 rows
            const int idx = tid + i * 256;
            const int r = idx >> 3, kc = idx & 7;
            CP_ASYNC16(so + GH_A_ARR + r * GH_ROWB + kc * 16,
                       Bh + (size_t)(bn + r) * K + k0 + kc * 8);
        }
    };

    load_stage(0, 0); CP_COMMIT();

    float acc[4][8][4];
#pragma unroll
    for (int a = 0; a < 4; a++)
#pragma unroll
        for (int b = 0; b < 8; b++)
#pragma unroll
            for (int c = 0; c < 4; c++) acc[a][b][c] = 0.f;

    for (int kt = 0; kt < NT; kt++) {
        if (kt + 1 < NT) load_stage((kt + 1) % 3, kt + 1);
        CP_COMMIT();
        CP_WAIT1();
        __syncthreads();

        const uint32_t s0 = sb + (kt % 3) * GH_STAGE;
#pragma unroll
        for (int kh = 0; kh < 4; kh++) {
            uint32_t a_f[4][4], b_f[4][4];
#pragma unroll
            for (int mt = 0; mt < 4; mt++) {
                const int row = warp_m * 64 + mt * 16 + (lane & 15);
                LDSM_X4(a_f[mt], s0 + row * GH_ROWB + kh * 32 + (lane >> 4) * 16);
            }
#pragma unroll
            for (int nt = 0; nt < 4; nt++) {
                const int row = warp_n * 64 + nt * 16 + (lane & 7) + ((lane >> 4) << 3);
                LDSM_X4(b_f[nt], s0 + GH_A_ARR + row * GH_ROWB + kh * 32 +
                                 ((lane >> 3) & 1) * 16);
            }
#pragma unroll
            for (int mt = 0; mt < 4; mt++)
#pragma unroll
                for (int j = 0; j < 8; j++)
                    MMA16816(acc[mt][j], a_f[mt],
                             b_f[j >> 1][(j & 1) * 2], b_f[j >> 1][(j & 1) * 2 + 1]);
        }
    }

    const int gq = lane >> 2, tq = lane & 3;
#pragma unroll
    for (int mt = 0; mt < 4; mt++) {
#pragma unroll
        for (int j = 0; j < 8; j++) {
            const int col = bn + warp_n * 64 + j * 8 + tq * 2;
            float2 bb = make_float2(0.f, 0.f);
            if (EPI == 2 || EPI == 3) bb = *(const float2*)&bias[col];
#pragma unroll
            for (int rr = 0; rr < 2; rr++) {
                const int row = bm + warp_m * 64 + mt * 16 + gq + rr * 8;
                float vx = acc[mt][j][rr * 2 + 0];
                float vy = acc[mt][j][rr * 2 + 1];
                if (EPI == 2 || EPI == 3) { vx += bb.x; vy += bb.y; }
                if (EPI == 2) { vx = gelu_exact(vx); vy = gelu_exact(vy); }
                if (EPI == 1 || EPI == 3) {
                    const float2 rv = *(const float2*)&res[(size_t)row * N + col];
                    vx += rv.x; vy += rv.y;
                }
                if (OUTMODE == 2) {
                    *(__half2*)&Ch[(size_t)row * N + col] = __floats2half2_rn(vx, vy);
                } else {
                    *(float2*)&C[(size_t)row * N + col] = make_float2(vx, vy);
                }
            }
        }
    }
}

// ---------------------------------------------------------------------------
// HMMA flash attention. Grid (T/128, H, B), 128 threads = 4 warps.
// 128-row Q tile; each warp owns 32 q-rows. K/V 64x64 tiles,
// 3-stage cp.async ring, ONE barrier per kv-tile.
// ---------------------------------------------------------------------------
#define AQ_S 72
#define ATT_Q     0
#define ATT_K(s)  (9216 + (s) * 4608)
#define ATT_V(s)  (23040 + (s) * 4608)
#define ATT_SMEM  (36864 * 2)          // 73728 B

__global__ __launch_bounds__(128, 2)
void attn_hmma(const __half* __restrict__ qkv, __half* __restrict__ ao) {
    extern __shared__ __half sh[];
    const uint32_t sb = smem_u32(sh);
    const int tid = threadIdx.x;
    const int lane = tid & 31, w = tid >> 5;
    const int b = blockIdx.z, h = blockIdx.y, qt = blockIdx.x;
    const int hoff = h * DHEAD;
    const int rowbase = b * TSEQ + qt * 128;

    // Load Q tile (128 rows x 64 halfs)
#pragma unroll
    for (int p = 0; p < 8; p++) {
        const int idx = tid + p * 128;
        const int r = idx >> 3, c8 = idx & 7;
        *(uint4*)(sh + ATT_Q + r * AQ_S + c8 * 8) =
            *(const uint4*)(qkv + (size_t)(rowbase + r) * 3072 + hoff + c8 * 8);
    }

    auto load_kv = [&](int st, int kt) {
        const int kvbase = b * TSEQ + kt * 64;
#pragma unroll
        for (int p = 0; p < 4; p++) {
            const int idx = tid + p * 128;
            const int r = idx >> 3, c8 = idx & 7;
            const __half* gk = qkv + (size_t)(kvbase + r) * 3072 + 1024 + hoff + c8 * 8;
            CP_ASYNC16(sb + 2 * (ATT_K(st) + r * AQ_S + c8 * 8), gk);
            CP_ASYNC16(sb + 2 * (ATT_V(st) + r * AQ_S + c8 * 8), gk + 1024);
        }
    };

    load_kv(0, 0); CP_COMMIT();
    __syncthreads();   // Q visibility (plain stores) before ldsm preload

    // Preload Q A-fragments: 2 row-groups x 4 k-steps
    uint32_t qa[2][4][4];
    const int m0 = w * 32;
#pragma unroll
    for (int mt = 0; mt < 2; mt++)
#pragma unroll
        for (int kk = 0; kk < 4; kk++) {
            const uint32_t ad = sb + 2 * (ATT_Q + (m0 + mt * 16 + (lane & 15)) * AQ_S +
                                          kk * 16 + (lane >> 4) * 8);
            LDSM_X4(qa[mt][kk], ad);
        }

    float m_[2][2], l_[2][2];
    float o[2][8][4];
#pragma unroll
    for (int mt = 0; mt < 2; mt++) {
        m_[mt][0] = -1e30f; m_[mt][1] = -1e30f;
        l_[mt][0] = 0.f;    l_[mt][1] = 0.f;
#pragma unroll
        for (int n = 0; n < 8; n++)
#pragma unroll
            for (int j = 0; j < 4; j++) o[mt][n][j] = 0.f;
    }

    const int NT = TSEQ / 64;
    for (int kt = 0; kt < NT; kt++) {
        if (kt + 1 < NT) load_kv((kt + 1) % 3, kt + 1);
        CP_COMMIT();
        CP_WAIT1();
        __syncthreads();
        const int s = kt % 3;

        // ---- S = Q K^T ----
        float c[2][8][4];
#pragma unroll
        for (int mt = 0; mt < 2; mt++)
#pragma unroll
            for (int n = 0; n < 8; n++)
#pragma unroll
                for (int j = 0; j < 4; j++) c[mt][n][j] = 0.f;

#pragma unroll
        for (int kk2 = 0; kk2 < 2; kk2++) {
#pragma unroll
            for (int n = 0; n < 8; n++) {
                uint32_t bf[4];
                const uint32_t ad = sb + 2 * (ATT_K(s) + (n * 8 + (lane & 7)) * AQ_S +
                                              kk2 * 32 + (lane >> 3) * 8);
                LDSM_X4(bf, ad);
#pragma unroll
                for (int mt = 0; mt < 2; mt++) {
                    MMA16816(c[mt][n], qa[mt][2 * kk2], bf[0], bf[1]);
                    MMA16816(c[mt][n], qa[mt][2 * kk2 + 1], bf[2], bf[3]);
                }
            }
        }

        // ---- online softmax per row-group ----
        uint32_t u01[2][8], u23[2][8];
#pragma unroll
        for (int mt = 0; mt < 2; mt++) {
            float tm0 = -1e30f, tm1 = -1e30f;
#pragma unroll
            for (int n = 0; n < 8; n++) {
                tm0 = fmaxf(tm0, fmaxf(c[mt][n][0], c[mt][n][1]));
                tm1 = fmaxf(tm1, fmaxf(c[mt][n][2], c[mt][n][3]));
            }
#pragma unroll
            for (int ofs = 1; ofs <= 2; ofs <<= 1) {
                tm0 = fmaxf(tm0, __shfl_xor_sync(0xffffffffu, tm0, ofs));
                tm1 = fmaxf(tm1, __shfl_xor_sync(0xffffffffu, tm1, ofs));
            }
            tm0 *= 0.125f; tm1 *= 0.125f;
            const float mn0 = fmaxf(m_[mt][0], tm0), mn1 = fmaxf(m_[mt][1], tm1);
            const float al0 = __expf(m_[mt][0] - mn0), al1 = __expf(m_[mt][1] - mn1);
            m_[mt][0] = mn0; m_[mt][1] = mn1;

            float rs0 = 0.f, rs1 = 0.f;
#pragma unroll
            for (int n = 0; n < 8; n++) {
                const float p0 = __expf(c[mt][n][0] * 0.125f - mn0);
                const float p1 = __expf(c[mt][n][1] * 0.125f - mn0);
                const float p2 = __expf(c[mt][n][2] * 0.125f - mn1);
                const float p3 = __expf(c[mt][n][3] * 0.125f - mn1);
                rs0 += p0 + p1; rs1 += p2 + p3;
                const __half2 h01 = __floats2half2_rn(p0, p1);
                const __half2 h23 = __floats2half2_rn(p2, p3);
                u01[mt][n] = *(const uint32_t*)&h01;
                u23[mt][n] = *(const uint32_t*)&h23;
            }
#pragma unroll
            for (int ofs = 1; ofs <= 2; ofs <<= 1) {
                rs0 += __shfl_xor_sync(0xffffffffu, rs0, ofs);
                rs1 += __shfl_xor_sync(0xffffffffu, rs1, ofs);
            }
            l_[mt][0] = l_[mt][0] * al0 + rs0;
            l_[mt][1] = l_[mt][1] * al1 + rs1;
#pragma unroll
            for (int n = 0; n < 8; n++) {
                o[mt][n][0] *= al0; o[mt][n][1] *= al0;
                o[mt][n][2] *= al1; o[mt][n][3] *= al1;
            }
        }

        // ---- O += P V (V fragments shared across row-groups) ----
#pragma unroll
        for (int kk = 0; kk < 4; kk++) {
            uint32_t au0[4] = {u01[0][2 * kk], u23[0][2 * kk],
                               u01[0][2 * kk + 1], u23[0][2 * kk + 1]};
            uint32_t au1[4] = {u01[1][2 * kk], u23[1][2 * kk],
                               u01[1][2 * kk + 1], u23[1][2 * kk + 1]};
#pragma unroll
            for (int n2 = 0; n2 < 4; n2++) {
                uint32_t bf[4];
                const uint32_t ad = sb + 2 * (ATT_V(s) + (kk * 16 + (lane & 15)) * AQ_S +
                                              n2 * 16 + (lane >> 4) * 8);
                LDSM_X4_T(bf, ad);
                MMA16816(o[0][2 * n2], au0, bf[0], bf[1]);
                MMA16816(o[0][2 * n2 + 1], au0, bf[2], bf[3]);
                MMA16816(o[1][2 * n2], au1, bf[0], bf[1]);
                MMA16816(o[1][2 * n2 + 1], au1, bf[2], bf[3]);
            }
        }
    }

    // ---- epilogue ----
    const int r0 = lane >> 2, tq = lane & 3;
#pragma unroll
    for (int mt = 0; mt < 2; mt++) {
        const float inv0 = 1.0f / l_[mt][0], inv1 = 1.0f / l_[mt][1];
        const int grow0 = rowbase + m0 + mt * 16 + r0, grow1 = grow0 + 8;
#pragma unroll
        for (int n = 0; n < 8; n++) {
            const int col = hoff + n * 8 + tq * 2;
            *(__half2*)&ao[(size_t)grow0 * DMODEL + col] =
                __floats2half2_rn(o[mt][n][0] * inv0, o[mt][n][1] * inv0);
            *(__half2*)&ao[(size_t)grow1 * DMODEL + col] =
                __floats2half2_rn(o[mt][n][2] * inv1, o[mt][n][3] * inv1);
        }
    }
}

// ---------------------------------------------------------------------------
// Launcher
// ---------------------------------------------------------------------------
extern "C" void kernel_launch(void* const* d_in, const int* in_sizes, int n_in,
                              void* d_out, int out_size) {
    const float* x     = (const float*)d_in[0];
    const float* ln1_s = (const float*)d_in[1];
    const float* ln1_b = (const float*)d_in[2];
    const float* qkv_w = (const float*)d_in[3];
    const float* out_w = (const float*)d_in[4];
    const float* ln2_s = (const float*)d_in[5];
    const float* ln2_b = (const float*)d_in[6];
    const float* fc1_w = (const float*)d_in[7];
    const float* fc1_b = (const float*)d_in[8];
    const float* fc2_w = (const float*)d_in[9];
    const float* fc2_b = (const float*)d_in[10];
    float* out = (float*)d_out;

    float *x1_p;
    __half *qkvh, *act, *ff, *wq, *wo, *w1, *w2;
    cudaGetSymbolAddress((void**)&x1_p, g_x1);
    cudaGetSymbolAddress((void**)&qkvh, g_qkvh);
    cudaGetSymbolAddress((void**)&act, g_act);
    cudaGetSymbolAddress((void**)&ff, g_ff);
    cudaGetSymbolAddress((void**)&wq, g_wqkv);
    cudaGetSymbolAddress((void**)&wo, g_wout);
    cudaGetSymbolAddress((void**)&w1, g_wfc1);
    cudaGetSymbolAddress((void**)&w2, g_wfc2);

    cudaFuncSetAttribute(gemm_hmma<0, 2>, cudaFuncAttributeMaxDynamicSharedMemorySize, GH_SMEM);
    cudaFuncSetAttribute(gemm_hmma<1, 0>, cudaFuncAttributeMaxDynamicSharedMemorySize, GH_SMEM);
    cudaFuncSetAttribute(gemm_hmma<2, 2>, cudaFuncAttributeMaxDynamicSharedMemorySize, GH_SMEM);
    cudaFuncSetAttribute(gemm_hmma<3, 0>, cudaFuncAttributeMaxDynamicSharedMemorySize, GH_SMEM);
    cudaFuncSetAttribute(attn_hmma, cudaFuncAttributeMaxDynamicSharedMemorySize, ATT_SMEM);

    // 0) Weight prep: fp32 -> fp16
    cvt_kernel<<<3 * DMODEL * DMODEL / 4 / 256, 256>>>(qkv_w, wq, 3 * DMODEL * DMODEL / 4);
    cvt_kernel<<<DMODEL * DMODEL / 4 / 256, 256>>>(out_w, wo, DMODEL * DMODEL / 4);
    cvt_kernel<<<DFF * DMODEL / 4 / 256, 256>>>(fc1_w, w1, DFF * DMODEL / 4);
    cvt_kernel<<<DMODEL * DFF / 4 / 256, 256>>>(fc2_w, w2, DMODEL * DFF / 4);

    // 1) LN1 -> fp16 activations
    ln_kernel<<<MROWS, 256>>>(x, ln1_s, ln1_b, act);

    // 2) QKV projection -> fp16
    gemm_hmma<0, 2><<<dim3(3 * DMODEL / 256, MROWS / 128), 256, GH_SMEM>>>(
        act, wq, nullptr, qkvh, MROWS, 3 * DMODEL, DMODEL, nullptr, nullptr);

    // 3) HMMA flash attention -> fp16
    attn_hmma<<<dim3(TSEQ / 128, NHEAD, BATCH), 128, ATT_SMEM>>>(qkvh, act);

    // 4) Out projection + residual -> x1 fp32
    gemm_hmma<1, 0><<<dim3(DMODEL / 256, MROWS / 128), 256, GH_SMEM>>>(
        act, wo, x1_p, nullptr, MROWS, DMODEL, DMODEL, nullptr, x);

    // 5) LN2 -> fp16 activations
    ln_kernel<<<MROWS, 256>>>(x1_p, ln2_s, ln2_b, act);

    // 6) FC1 + bias + GELU -> fp16
    gemm_hmma<2, 2><<<dim3(DFF / 256, MROWS / 128), 256, GH_SMEM>>>(
        act, w1, nullptr, ff, MROWS, DFF, DMODEL, fc1_b, nullptr);

    // 7) FC2 + bias + residual -> out fp32
    gemm_hmma<3, 0><<<dim3(DMODEL / 256, MROWS / 128), 256, GH_SMEM>>>(
        ff, w2, out, nullptr, MROWS, DMODEL, DFF, fc2_b, x1_p);
}